// round 7
// baseline (speedup 1.0000x reference)
#include <cuda_runtime.h>
#include <cuda_bf16.h>
#include <math.h>
#include <stdint.h>

#define N_NODES 100000
#define N_EDGES 1600000
#define T_STEPS 64
#define D 256
#define D_OUT 16
#define CHUNK 1562
#define NB_SCAN 98
#define GRU_NB 32
#define GRU_UPB 8
#define POOL_PARTS 16

// ---------------- scratch ---------------------------------------------------
__device__ __align__(16) int   g_cnt[N_NODES];
__device__ __align__(16) float g_dis[N_NODES];
__device__ __align__(16) int   g_row_ptr[N_NODES + 1];
__device__ __align__(16) int   g_cursor[N_NODES];
__device__ __align__(16) int   g_csr_src[N_EDGES];
__device__ __align__(16) float g_csr_coef[N_EDGES];
__device__ __align__(16) float g_bufA[(size_t)N_NODES * D];   // GEMM out (fp32)
__device__ __align__(16) float g_bufB[(size_t)N_NODES * D];   // layer-2 GCN out
__device__ __align__(16) __nv_bfloat16 g_a_hi[(size_t)N_NODES * D];  // A split
__device__ __align__(16) __nv_bfloat16 g_a_lo[(size_t)N_NODES * D];
__device__ __align__(16) __nv_bfloat16 g_b_hi[D * D];                // W^T split [N][K]
__device__ __align__(16) __nv_bfloat16 g_b_lo[D * D];
__device__ __align__(16) float g_pooled[T_STEPS * D];
__device__ __align__(16) float g_ppart[T_STEPS][POOL_PARTS][D];
__device__ __align__(16) float g_gx[T_STEPS * 3 * D];
__device__ __align__(16) int   g_blocksums[128];
__device__ volatile int   g_gru_flag[T_STEPS + 2][GRU_NB];
__device__ volatile float g_h[D];

// ---------------- CSR build ------------------------------------------------
__global__ void k_zero_cnt() {
    int i = blockIdx.x * blockDim.x + threadIdx.x;
    if (i < N_NODES) g_cnt[i] = 0;
}
__global__ void k_hist(const int* __restrict__ dst) {
    int e = blockIdx.x * blockDim.x + threadIdx.x;
    if (e < N_EDGES) {
        int d = dst[e];
        if (d >= 0 && d < N_NODES) atomicAdd(&g_cnt[d], 1);
    }
}
__global__ void k_scan1() {
    __shared__ int sh[256];
    int b = blockIdx.x, tid = threadIdx.x;
    int base = b * 1024;
    int v[4];
#pragma unroll
    for (int i = 0; i < 4; i++) {
        int idx = base + tid * 4 + i;
        v[i] = (idx < N_NODES) ? g_cnt[idx] : 0;
    }
    int s = v[0] + v[1] + v[2] + v[3];
    sh[tid] = s;
    __syncthreads();
    for (int off = 1; off < 256; off <<= 1) {
        int x = (tid >= off) ? sh[tid - off] : 0;
        __syncthreads();
        sh[tid] += x;
        __syncthreads();
    }
    int excl = sh[tid] - s;
    if (tid == 255) g_blocksums[b] = sh[255];
    int run = excl;
#pragma unroll
    for (int i = 0; i < 4; i++) {
        int idx = base + tid * 4 + i;
        if (idx < N_NODES) g_row_ptr[idx] = run;
        run += v[i];
    }
}
__global__ void k_scan2(int nb) {
    __shared__ int sh[128];
    int tid = threadIdx.x;
    int s = (tid < nb) ? g_blocksums[tid] : 0;
    sh[tid] = s;
    __syncthreads();
    for (int off = 1; off < 128; off <<= 1) {
        int x = (tid >= off) ? sh[tid - off] : 0;
        __syncthreads();
        sh[tid] += x;
        __syncthreads();
    }
    if (tid < nb) g_blocksums[tid] = sh[tid] - s;
}
__global__ void k_scan3() {
    int i = blockIdx.x * blockDim.x + threadIdx.x;
    if (i < N_NODES) {
        int v = g_row_ptr[i] + g_blocksums[i >> 10];
        g_row_ptr[i] = v;
        g_cursor[i]  = v;
        g_dis[i] = rsqrtf((float)g_cnt[i] + 1.0f);
    }
    if (i == 0) g_row_ptr[N_NODES] = N_EDGES;
}
__global__ void k_scatter(const int* __restrict__ src, const int* __restrict__ dst) {
    int e = blockIdx.x * blockDim.x + threadIdx.x;
    if (e < N_EDGES) {
        int s = src[e], d = dst[e];
        if (s < 0 || s >= N_NODES || d < 0 || d >= N_NODES) return;
        int p = atomicAdd(&g_cursor[d], 1);
        g_csr_src[p]  = s;
        g_csr_coef[p] = g_dis[s] * g_dis[d];
    }
}

// ---------------- input split prep -----------------------------------------
__global__ void k_prep_x(const float* __restrict__ x) {
    int i = blockIdx.x * blockDim.x + threadIdx.x;   // float2 index
    if (i >= N_NODES * 128) return;
    float2 v = ((const float2*)x)[i];
    __nv_bfloat16 hx = __float2bfloat16(v.x);
    __nv_bfloat16 hy = __float2bfloat16(v.y);
    __nv_bfloat162 hi; hi.x = hx; hi.y = hy;
    __nv_bfloat162 lo;
    lo.x = __float2bfloat16(v.x - __bfloat162float(hx));
    lo.y = __float2bfloat16(v.y - __bfloat162float(hy));
    ((__nv_bfloat162*)g_a_hi)[i] = hi;
    ((__nv_bfloat162*)g_a_lo)[i] = lo;
}
// W [K,N] row-major -> W^T [N][K] bf16 hi/lo
__global__ void k_prep_w(const float* __restrict__ W) {
    int idx = blockIdx.x * blockDim.x + threadIdx.x;  // n*256 + k
    if (idx >= D * D) return;
    int n = idx >> 8, k = idx & 255;
    float w = W[k * D + n];
    __nv_bfloat16 hi = __float2bfloat16(w);
    g_b_hi[idx] = hi;
    g_b_lo[idx] = __float2bfloat16(w - __bfloat162float(hi));
}

// ---------------- bf16x3 tensor GEMM via mma.sync.m16n8k16 ------------------
// block 128(M) x 64(N), 8 warps = 4Mx2N, warp tile 32x32, BK=32.
// A/B pre-split bf16 in global; fragments loaded as packed b32 (no cvt in loop).
#define APITCH 40   // bf16 elems; bank = row*20+lr mod 32 -> conflict-free frags
#define BPITCH 40

__device__ __forceinline__ void mma_bf16(float* c, const uint32_t* a, const uint32_t* b) {
    asm volatile(
        "mma.sync.aligned.m16n8k16.row.col.f32.bf16.bf16.f32 "
        "{%0,%1,%2,%3}, {%4,%5,%6,%7}, {%8,%9}, {%0,%1,%2,%3};"
        : "+f"(c[0]), "+f"(c[1]), "+f"(c[2]), "+f"(c[3])
        : "r"(a[0]), "r"(a[1]), "r"(a[2]), "r"(a[3]), "r"(b[0]), "r"(b[1]));
}

__global__ __launch_bounds__(256)
void k_gemm_bf(int M) {
    __shared__ __nv_bfloat16 Ah[128][APITCH];
    __shared__ __nv_bfloat16 Al[128][APITCH];
    __shared__ __nv_bfloat16 Bh[64][BPITCH];
    __shared__ __nv_bfloat16 Bl[64][BPITCH];

    int bm = blockIdx.y * 128;
    int bn = blockIdx.x * 64;
    int tid  = threadIdx.x;
    int warp = tid >> 5, lane = tid & 31;
    int wm = warp & 3;
    int wn = warp >> 2;
    int lq = lane >> 2;     // 0..7
    int lr = lane & 3;      // 0..3

    float acc[2][4][4];
#pragma unroll
    for (int i = 0; i < 2; i++)
#pragma unroll
        for (int j = 0; j < 4; j++)
#pragma unroll
            for (int v = 0; v < 4; v++) acc[i][j][v] = 0.f;

    for (int ch = 0; ch < 8; ch++) {
        int k0 = ch * 32;
        // A chunk: 128 rows x 32 bf16, hi+lo (uint4 = 8 bf16)
#pragma unroll
        for (int i = 0; i < 2; i++) {
            int idx = tid + 256 * i;          // 0..511
            int row = idx & 127, c16 = idx >> 7;   // c16 0..3
            uint4 vh = make_uint4(0, 0, 0, 0), vl = make_uint4(0, 0, 0, 0);
            if (bm + row < M) {
                size_t g = (size_t)(bm + row) * D + k0 + c16 * 8;
                vh = *(const uint4*)(g_a_hi + g);
                vl = *(const uint4*)(g_a_lo + g);
            }
            *(uint4*)&Ah[row][c16 * 8] = vh;
            *(uint4*)&Al[row][c16 * 8] = vl;
        }
        // B chunk: 64 n-rows x 32 bf16, hi+lo
        {
            int row = tid & 63, c16 = tid >> 6;    // c16 0..3
            size_t g = (size_t)(bn + row) * D + k0 + c16 * 8;
            *(uint4*)&Bh[row][c16 * 8] = *(const uint4*)(g_b_hi + g);
            *(uint4*)&Bl[row][c16 * 8] = *(const uint4*)(g_b_lo + g);
        }
        __syncthreads();

#pragma unroll
        for (int ks = 0; ks < 2; ks++) {
            int kk = ks * 16;
            uint32_t aH[2][4], aL[2][4], bH[4][2], bL[4][2];
#pragma unroll
            for (int mt = 0; mt < 2; mt++) {
                int r = wm * 32 + mt * 16 + lq;
                aH[mt][0] = *(const uint32_t*)&Ah[r    ][kk + lr * 2];
                aH[mt][1] = *(const uint32_t*)&Ah[r + 8][kk + lr * 2];
                aH[mt][2] = *(const uint32_t*)&Ah[r    ][kk + 8 + lr * 2];
                aH[mt][3] = *(const uint32_t*)&Ah[r + 8][kk + 8 + lr * 2];
                aL[mt][0] = *(const uint32_t*)&Al[r    ][kk + lr * 2];
                aL[mt][1] = *(const uint32_t*)&Al[r + 8][kk + lr * 2];
                aL[mt][2] = *(const uint32_t*)&Al[r    ][kk + 8 + lr * 2];
                aL[mt][3] = *(const uint32_t*)&Al[r + 8][kk + 8 + lr * 2];
            }
#pragma unroll
            for (int nt = 0; nt < 4; nt++) {
                int n = wn * 32 + nt * 8 + lq;
                bH[nt][0] = *(const uint32_t*)&Bh[n][kk + lr * 2];
                bH[nt][1] = *(const uint32_t*)&Bh[n][kk + 8 + lr * 2];
                bL[nt][0] = *(const uint32_t*)&Bl[n][kk + lr * 2];
                bL[nt][1] = *(const uint32_t*)&Bl[n][kk + 8 + lr * 2];
            }
#pragma unroll
            for (int mt = 0; mt < 2; mt++)
#pragma unroll
                for (int nt = 0; nt < 4; nt++) {
                    mma_bf16(acc[mt][nt], aL[mt], bH[nt]);
                    mma_bf16(acc[mt][nt], aH[mt], bL[nt]);
                    mma_bf16(acc[mt][nt], aH[mt], bH[nt]);
                }
        }
        __syncthreads();
    }

    // epilogue: fp32 -> g_bufA (C layout identical to m16n8k8)
#pragma unroll
    for (int mt = 0; mt < 2; mt++) {
#pragma unroll
        for (int nt = 0; nt < 4; nt++) {
            int gr0 = bm + wm * 32 + mt * 16 + lq;
            int gc  = bn + wn * 32 + nt * 8 + lr * 2;
            if (gr0 < M)
                *(float2*)(g_bufA + (size_t)gr0 * D + gc) =
                    make_float2(acc[mt][nt][0], acc[mt][nt][1]);
            if (gr0 + 8 < M)
                *(float2*)(g_bufA + (size_t)(gr0 + 8) * D + gc) =
                    make_float2(acc[mt][nt][2], acc[mt][nt][3]);
        }
    }
}

// ---------------- fused GCN aggregation, feature-sliced --------------------
// mode 0: emit bf16 hi/lo split (feeds next GEMM). mode 1: fp32 -> g_bufB.
__global__ __launch_bounds__(64)
void k_gcn(const float* __restrict__ bias, int mode) {
    int d   = blockIdx.x;
    int fo  = blockIdx.y * 64 + threadIdx.x;
    int beg = g_row_ptr[d], end = g_row_ptr[d + 1];
    const float2* xw2 = (const float2*)g_bufA;
    float2 acc = make_float2(0.f, 0.f);
    int j = beg;
    for (; j + 3 < end; j += 4) {
        int s0 = g_csr_src[j],     s1 = g_csr_src[j + 1];
        int s2 = g_csr_src[j + 2], s3 = g_csr_src[j + 3];
        float c0 = g_csr_coef[j],     c1 = g_csr_coef[j + 1];
        float c2 = g_csr_coef[j + 2], c3 = g_csr_coef[j + 3];
        float2 v0 = xw2[(size_t)s0 * 128 + fo];
        float2 v1 = xw2[(size_t)s1 * 128 + fo];
        float2 v2 = xw2[(size_t)s2 * 128 + fo];
        float2 v3 = xw2[(size_t)s3 * 128 + fo];
        acc.x += c0 * v0.x + c1 * v1.x + c2 * v2.x + c3 * v3.x;
        acc.y += c0 * v0.y + c1 * v1.y + c2 * v2.y + c3 * v3.y;
    }
    for (; j < end; j++) {
        int s = g_csr_src[j];
        float c = g_csr_coef[j];
        float2 v = xw2[(size_t)s * 128 + fo];
        acc.x += c * v.x;
        acc.y += c * v.y;
    }
    float dis = g_dis[d];
    float d2 = dis * dis;
    float2 sv = xw2[(size_t)d * 128 + fo];
    acc.x += d2 * sv.x + bias[fo * 2];
    acc.y += d2 * sv.y + bias[fo * 2 + 1];
    acc.x = fmaxf(acc.x, 0.f);
    acc.y = fmaxf(acc.y, 0.f);
    if (mode == 1) {
        ((float2*)g_bufB)[(size_t)d * 128 + fo] = acc;
    } else {
        __nv_bfloat16 hx = __float2bfloat16(acc.x);
        __nv_bfloat16 hy = __float2bfloat16(acc.y);
        __nv_bfloat162 hi; hi.x = hx; hi.y = hy;
        __nv_bfloat162 lo;
        lo.x = __float2bfloat16(acc.x - __bfloat162float(hx));
        lo.y = __float2bfloat16(acc.y - __bfloat162float(hy));
        ((__nv_bfloat162*)g_a_hi)[(size_t)d * 128 + fo] = hi;
        ((__nv_bfloat162*)g_a_lo)[(size_t)d * 128 + fo] = lo;
    }
}

// ---------------- segment mean pool (two-phase) ----------------------------
__global__ void k_pool1() {
    int t = blockIdx.x >> 4;
    int p = blockIdx.x & 15;
    int f = threadIdx.x;
    int r0 = p * 98;
    int r1 = r0 + 98; if (r1 > CHUNK) r1 = CHUNK;
    const float* base = g_bufB + ((size_t)t * CHUNK + r0) * D;
    float acc = 0.f;
#pragma unroll 4
    for (int i = 0; i < r1 - r0; i++) acc += base[(size_t)i * D + f];
    g_ppart[t][p][f] = acc;
}
__global__ void k_pool2() {
    int t = blockIdx.x, f = threadIdx.x;
    float acc = 0.f;
#pragma unroll
    for (int p = 0; p < POOL_PARTS; p++) acc += g_ppart[t][p][f];
    g_pooled[t * D + f] = acc * (1.0f / (float)CHUNK);
}

// ---------------- gx = pooled @ w_ih^T + b_ih ------------------------------
__global__ void k_gx(const float* __restrict__ w_ih, const float* __restrict__ b_ih) {
    int idx = blockIdx.x * blockDim.x + threadIdx.x;
    if (idx >= T_STEPS * 3 * D) return;
    int t = idx / (3 * D), j = idx % (3 * D);
    const float4* w = (const float4*)(w_ih + (size_t)j * D);
    const float4* p = (const float4*)(g_pooled + t * D);
    float acc = b_ih[j];
#pragma unroll 4
    for (int k = 0; k < D / 4; k++) {
        float4 a = w[k], b = p[k];
        acc += a.x * b.x + a.y * b.y + a.z * b.z + a.w * b.w;
    }
    g_gx[idx] = acc;
}

// ---------------- distributed GRU ------------------------------------------
__global__ void k_gru_reset() {
    int i = blockIdx.x * blockDim.x + threadIdx.x;
    if (i < (T_STEPS + 2) * GRU_NB) ((volatile int*)g_gru_flag)[i] = 0;
}
__device__ __forceinline__ void gru_barrier(int id, int b, int tid) {
    __syncthreads();
    if (tid == 0) {
        __threadfence();
        g_gru_flag[id][b] = 1;
    }
    if (tid < GRU_NB) {
        while (g_gru_flag[id][tid] == 0) { }
    }
    __syncthreads();
}
__global__ __launch_bounds__(256)
void k_gru(const float* __restrict__ w_hh, const float* __restrict__ b_hh,
           const float* __restrict__ Wc, const float* __restrict__ bc,
           float* __restrict__ out) {
    __shared__ float w_sh[3 * GRU_UPB][D];
    __shared__ float h_sh[D];
    __shared__ float gh_sh[3 * GRU_UPB];
    __shared__ float bhh_sh[3 * GRU_UPB];
    int b = blockIdx.x, tid = threadIdx.x;
    int warp = tid >> 5, lane = tid & 31;

    for (int idx = tid; idx < 3 * GRU_UPB * D; idx += 256) {
        int l = idx >> 8, k = idx & 255;
        int row = (l >> 3) * D + b * GRU_UPB + (l & 7);
        w_sh[l][k] = w_hh[(size_t)row * D + k];
    }
    if (tid < 3 * GRU_UPB) {
        int row = (tid >> 3) * D + b * GRU_UPB + (tid & 7);
        bhh_sh[tid] = b_hh[row];
    }
    if (tid < GRU_UPB) g_h[b * GRU_UPB + tid] = 0.f;
    __threadfence();
    gru_barrier(0, b, tid);

    for (int t = 0; t < T_STEPS; t++) {
        h_sh[tid] = g_h[tid];
        __syncthreads();
#pragma unroll
        for (int rr = 0; rr < 3; rr++) {
            int l = warp * 3 + rr;
            const float4* w = (const float4*)&w_sh[l][lane * 8];
            float4 a0 = w[0], a1 = w[1];
            float4 h0 = *(const float4*)&h_sh[lane * 8];
            float4 h1 = *(const float4*)&h_sh[lane * 8 + 4];
            float p = a0.x * h0.x + a0.y * h0.y + a0.z * h0.z + a0.w * h0.w
                    + a1.x * h1.x + a1.y * h1.y + a1.z * h1.z + a1.w * h1.w;
#pragma unroll
            for (int o = 16; o > 0; o >>= 1) p += __shfl_down_sync(0xffffffffu, p, o);
            if (lane == 0) gh_sh[l] = p + bhh_sh[l];
        }
        __syncthreads();
        if (tid < GRU_UPB) {
            int u = b * GRU_UPB + tid;
            float xr = g_gx[t * 3 * D + u];
            float xz = g_gx[t * 3 * D + D + u];
            float xn = g_gx[t * 3 * D + 2 * D + u];
            float r_ = 1.f / (1.f + expf(-(xr + gh_sh[tid])));
            float z_ = 1.f / (1.f + expf(-(xz + gh_sh[GRU_UPB + tid])));
            float n_ = tanhf(xn + r_ * gh_sh[2 * GRU_UPB + tid]);
            g_h[u] = (1.f - z_) * n_ + z_ * h_sh[u];
        }
        __threadfence();
        gru_barrier(t + 1, b, tid);
    }
    if (b == 0 && tid < D_OUT) {
        float acc = bc[tid];
        for (int k = 0; k < D; k++) acc += Wc[(size_t)tid * D + k] * g_h[k];
        out[tid] = acc;
    }
}

// ---------------- launch ----------------------------------------------------
extern "C" void kernel_launch(void* const* d_in, const int* in_sizes, int n_in,
                              void* d_out, int out_size) {
    int idx_x = 0, idx_ei = 1;
    if (in_sizes[idx_ei] != 2 * N_EDGES) {
        for (int i = 0; i < n_in; i++) if (in_sizes[i] == 2 * N_EDGES) { idx_ei = i; break; }
    }
    if (in_sizes[idx_x] != N_NODES * D) {
        for (int i = 0; i < n_in; i++) if (in_sizes[i] == N_NODES * D) { idx_x = i; break; }
    }

    const float* x    = (const float*)d_in[idx_x];
    const int*   ei   = (const int*)d_in[idx_ei];
    const float* W1   = (const float*)d_in[3];
    const float* b1   = (const float*)d_in[4];
    const float* W2   = (const float*)d_in[5];
    const float* b2   = (const float*)d_in[6];
    const float* w_ih = (const float*)d_in[7];
    const float* w_hh = (const float*)d_in[8];
    const float* b_ih = (const float*)d_in[9];
    const float* b_hh = (const float*)d_in[10];
    const float* Wc   = (const float*)d_in[11];
    const float* bc   = (const float*)d_in[12];
    float* out = (float*)d_out;

    const int* src = ei;
    const int* dst = ei + N_EDGES;

    // CSR by dst (counting sort), deg_inv_sqrt
    k_zero_cnt<<<(N_NODES + 255) / 256, 256>>>();
    k_hist<<<(N_EDGES + 255) / 256, 256>>>(dst);
    k_scan1<<<NB_SCAN, 256>>>();
    k_scan2<<<1, 128>>>(NB_SCAN);
    k_scan3<<<(N_NODES + 255) / 256, 256>>>();
    k_scatter<<<(N_EDGES + 255) / 256, 256>>>(src, dst);

    dim3 gemmGrid(4, (N_NODES + 127) / 128);
    dim3 gcnGrid(N_NODES, 2);

    // layer 1: split inputs, bf16x3 tensor GEMM, gather (emit bf16 split)
    k_prep_x<<<(N_NODES * 128 + 255) / 256, 256>>>(x);
    k_prep_w<<<(D * D + 255) / 256, 256>>>(W1);
    k_gemm_bf<<<gemmGrid, 256>>>(N_NODES);
    k_gcn<<<gcnGrid, 64>>>(b1, 0);

    // layer 2
    k_prep_w<<<(D * D + 255) / 256, 256>>>(W2);
    k_gemm_bf<<<gemmGrid, 256>>>(N_NODES);
    k_gcn<<<gcnGrid, 64>>>(b2, 1);

    // pool -> gx -> GRU(+classifier)
    k_pool1<<<T_STEPS * POOL_PARTS, 256>>>();
    k_pool2<<<T_STEPS, 256>>>();
    k_gx<<<(T_STEPS * 3 * D + 127) / 128, 128>>>(w_ih, b_ih);
    k_gru_reset<<<((T_STEPS + 2) * GRU_NB + 255) / 256, 256>>>();
    k_gru<<<GRU_NB, 256>>>(w_hh, b_hh, Wc, bc, out);
}

// round 8
// speedup vs baseline: 1.2676x; 1.2676x over previous
#include <cuda_runtime.h>
#include <cuda_bf16.h>
#include <cuda_fp16.h>
#include <math.h>
#include <stdint.h>

#define N_NODES 100000
#define N_EDGES 1600000
#define T_STEPS 64
#define D 256
#define D_OUT 16
#define CHUNK 1562
#define NB_SCAN 98
#define GRU_NB 32
#define GRU_UPB 8
#define POOL_PARTS 16

// ---------------- scratch ---------------------------------------------------
__device__ __align__(16) int   g_cnt[N_NODES];
__device__ __align__(16) float g_dis[N_NODES];
__device__ __align__(16) int   g_row_ptr[N_NODES + 1];
__device__ __align__(16) int   g_cursor[N_NODES];
__device__ __align__(16) int   g_csr_src[N_EDGES];
__device__ __align__(16) float g_csr_coef[N_EDGES];
__device__ __align__(16) float g_bufA[(size_t)N_NODES * D];   // GEMM out (fp32)
__device__ __align__(16) float g_bufB[(size_t)N_NODES * D];   // layer-2 GCN out
__device__ __align__(16) __half g_a16[(size_t)N_NODES * D];   // GEMM A (fp16 single)
__device__ __align__(16) __half g_bh16[D * D];                // W^T hi [N][K]
__device__ __align__(16) __half g_bl16[D * D];                // W^T lo*4096 [N][K]
__device__ __align__(16) float g_pooled[T_STEPS * D];
__device__ __align__(16) float g_ppart[T_STEPS][POOL_PARTS][D];
__device__ __align__(16) float g_gx[T_STEPS * 3 * D];
__device__ __align__(16) int   g_blocksums[128];
__device__ volatile int   g_gru_flag[T_STEPS + 2][GRU_NB];
__device__ volatile float g_h[D];

// ---------------- CSR build ------------------------------------------------
__global__ void k_zero_cnt() {
    int i = blockIdx.x * blockDim.x + threadIdx.x;
    if (i < N_NODES) g_cnt[i] = 0;
}
__global__ void k_hist(const int* __restrict__ dst) {
    int e = blockIdx.x * blockDim.x + threadIdx.x;
    if (e < N_EDGES) {
        int d = dst[e];
        if (d >= 0 && d < N_NODES) atomicAdd(&g_cnt[d], 1);
    }
}
__global__ void k_scan1() {
    __shared__ int sh[256];
    int b = blockIdx.x, tid = threadIdx.x;
    int base = b * 1024;
    int v[4];
#pragma unroll
    for (int i = 0; i < 4; i++) {
        int idx = base + tid * 4 + i;
        v[i] = (idx < N_NODES) ? g_cnt[idx] : 0;
    }
    int s = v[0] + v[1] + v[2] + v[3];
    sh[tid] = s;
    __syncthreads();
    for (int off = 1; off < 256; off <<= 1) {
        int x = (tid >= off) ? sh[tid - off] : 0;
        __syncthreads();
        sh[tid] += x;
        __syncthreads();
    }
    int excl = sh[tid] - s;
    if (tid == 255) g_blocksums[b] = sh[255];
    int run = excl;
#pragma unroll
    for (int i = 0; i < 4; i++) {
        int idx = base + tid * 4 + i;
        if (idx < N_NODES) g_row_ptr[idx] = run;
        run += v[i];
    }
}
__global__ void k_scan2(int nb) {
    __shared__ int sh[128];
    int tid = threadIdx.x;
    int s = (tid < nb) ? g_blocksums[tid] : 0;
    sh[tid] = s;
    __syncthreads();
    for (int off = 1; off < 128; off <<= 1) {
        int x = (tid >= off) ? sh[tid - off] : 0;
        __syncthreads();
        sh[tid] += x;
        __syncthreads();
    }
    if (tid < nb) g_blocksums[tid] = sh[tid] - s;
}
__global__ void k_scan3() {
    int i = blockIdx.x * blockDim.x + threadIdx.x;
    if (i < N_NODES) {
        int v = g_row_ptr[i] + g_blocksums[i >> 10];
        g_row_ptr[i] = v;
        g_cursor[i]  = v;
        g_dis[i] = rsqrtf((float)g_cnt[i] + 1.0f);
    }
    if (i == 0) g_row_ptr[N_NODES] = N_EDGES;
}
__global__ void k_scatter(const int* __restrict__ src, const int* __restrict__ dst) {
    int e = blockIdx.x * blockDim.x + threadIdx.x;
    if (e < N_EDGES) {
        int s = src[e], d = dst[e];
        if (s < 0 || s >= N_NODES || d < 0 || d >= N_NODES) return;
        int p = atomicAdd(&g_cursor[d], 1);
        g_csr_src[p]  = s;
        g_csr_coef[p] = g_dis[s] * g_dis[d];
    }
}

// ---------------- input prep -----------------------------------------------
__global__ void k_prep_x(const float* __restrict__ x) {
    int i = blockIdx.x * blockDim.x + threadIdx.x;   // float2 index
    if (i >= N_NODES * 128) return;
    float2 v = ((const float2*)x)[i];
    __half2 h;
    h.x = __float2half(v.x);
    h.y = __float2half(v.y);
    ((__half2*)g_a16)[i] = h;
}
// W [K,N] row-major -> W^T [N][K]; hi fp16, lo = (w-hi)*4096 fp16
__global__ void k_prep_w(const float* __restrict__ W) {
    int idx = blockIdx.x * blockDim.x + threadIdx.x;  // n*256 + k
    if (idx >= D * D) return;
    int n = idx >> 8, k = idx & 255;
    float w = W[k * D + n];
    __half hi = __float2half(w);
    float resid = (w - __half2float(hi)) * 4096.0f;
    g_bh16[idx] = hi;
    g_bl16[idx] = __float2half(resid);
}

// ---------------- fp16 2-pass tensor GEMM (A single, W split) ---------------
// block 128(M) x 64(N), 8 warps = 4Mx2N, warp tile 32x32, BK=32.
// C = A·Whi + (A·Wlo)*2^-12, dual fp32 accumulators.
#define APITCH 40

__device__ __forceinline__ void mma_f16(float* c, const uint32_t* a, const uint32_t* b) {
    asm volatile(
        "mma.sync.aligned.m16n8k16.row.col.f32.f16.f16.f32 "
        "{%0,%1,%2,%3}, {%4,%5,%6,%7}, {%8,%9}, {%0,%1,%2,%3};"
        : "+f"(c[0]), "+f"(c[1]), "+f"(c[2]), "+f"(c[3])
        : "r"(a[0]), "r"(a[1]), "r"(a[2]), "r"(a[3]), "r"(b[0]), "r"(b[1]));
}

__global__ __launch_bounds__(256)
void k_gemm_f16(int M) {
    __shared__ __half Ah[128][APITCH];
    __shared__ __half Bh[64][APITCH];
    __shared__ __half Bl[64][APITCH];

    int bm = blockIdx.y * 128;
    int bn = blockIdx.x * 64;
    int tid  = threadIdx.x;
    int warp = tid >> 5, lane = tid & 31;
    int wm = warp & 3;
    int wn = warp >> 2;
    int lq = lane >> 2;
    int lr = lane & 3;

    float accM[2][4][4], accC[2][4][4];
#pragma unroll
    for (int i = 0; i < 2; i++)
#pragma unroll
        for (int j = 0; j < 4; j++)
#pragma unroll
            for (int v = 0; v < 4; v++) { accM[i][j][v] = 0.f; accC[i][j][v] = 0.f; }

    for (int ch = 0; ch < 8; ch++) {
        int k0 = ch * 32;
        // A chunk: 128 rows x 32 fp16 (64B/row = 4 x 16B); 512 chunks, 2/thread
#pragma unroll
        for (int i = 0; i < 2; i++) {
            int idx = tid + 256 * i;
            int row = idx >> 2, c = idx & 3;
            uint4 v = make_uint4(0, 0, 0, 0);
            if (bm + row < M)
                v = *(const uint4*)(g_a16 + (size_t)(bm + row) * D + k0 + c * 8);
            *(uint4*)&Ah[row][c * 8] = v;
        }
        // B chunks: 64 n-rows x 32 fp16, hi and lo; 256 chunks each, 1/thread
        {
            int row = tid >> 2, c = tid & 3;
            size_t g = (size_t)(bn + row) * D + k0 + c * 8;
            *(uint4*)&Bh[row][c * 8] = *(const uint4*)(g_bh16 + g);
            *(uint4*)&Bl[row][c * 8] = *(const uint4*)(g_bl16 + g);
        }
        __syncthreads();

#pragma unroll
        for (int ks = 0; ks < 2; ks++) {
            int kk = ks * 16;
            uint32_t a[2][4], bH[4][2], bL[4][2];
#pragma unroll
            for (int mt = 0; mt < 2; mt++) {
                int r = wm * 32 + mt * 16 + lq;
                a[mt][0] = *(const uint32_t*)&Ah[r    ][kk + lr * 2];
                a[mt][1] = *(const uint32_t*)&Ah[r + 8][kk + lr * 2];
                a[mt][2] = *(const uint32_t*)&Ah[r    ][kk + 8 + lr * 2];
                a[mt][3] = *(const uint32_t*)&Ah[r + 8][kk + 8 + lr * 2];
            }
#pragma unroll
            for (int nt = 0; nt < 4; nt++) {
                int n = wn * 32 + nt * 8 + lq;
                bH[nt][0] = *(const uint32_t*)&Bh[n][kk + lr * 2];
                bH[nt][1] = *(const uint32_t*)&Bh[n][kk + 8 + lr * 2];
                bL[nt][0] = *(const uint32_t*)&Bl[n][kk + lr * 2];
                bL[nt][1] = *(const uint32_t*)&Bl[n][kk + 8 + lr * 2];
            }
#pragma unroll
            for (int mt = 0; mt < 2; mt++)
#pragma unroll
                for (int nt = 0; nt < 4; nt++) {
                    mma_f16(accM[mt][nt], a[mt], bH[nt]);
                    mma_f16(accC[mt][nt], a[mt], bL[nt]);
                }
        }
        __syncthreads();
    }

    const float s = 1.0f / 4096.0f;
#pragma unroll
    for (int mt = 0; mt < 2; mt++) {
#pragma unroll
        for (int nt = 0; nt < 4; nt++) {
            int gr0 = bm + wm * 32 + mt * 16 + lq;
            int gc  = bn + wn * 32 + nt * 8 + lr * 2;
            float v0 = accM[mt][nt][0] + accC[mt][nt][0] * s;
            float v1 = accM[mt][nt][1] + accC[mt][nt][1] * s;
            float v2 = accM[mt][nt][2] + accC[mt][nt][2] * s;
            float v3 = accM[mt][nt][3] + accC[mt][nt][3] * s;
            if (gr0 < M)
                *(float2*)(g_bufA + (size_t)gr0 * D + gc) = make_float2(v0, v1);
            if (gr0 + 8 < M)
                *(float2*)(g_bufA + (size_t)(gr0 + 8) * D + gc) = make_float2(v2, v3);
        }
    }
}

// ---------------- fused GCN aggregation, feature-sliced --------------------
// mode 0: emit fp16 (feeds next GEMM). mode 1: fp32 -> g_bufB.
__global__ __launch_bounds__(64)
void k_gcn(const float* __restrict__ bias, int mode) {
    int d   = blockIdx.x;
    int fo  = blockIdx.y * 64 + threadIdx.x;
    int beg = g_row_ptr[d], end = g_row_ptr[d + 1];
    const float2* xw2 = (const float2*)g_bufA;
    float2 acc = make_float2(0.f, 0.f);
    int j = beg;
    for (; j + 3 < end; j += 4) {
        int s0 = g_csr_src[j],     s1 = g_csr_src[j + 1];
        int s2 = g_csr_src[j + 2], s3 = g_csr_src[j + 3];
        float c0 = g_csr_coef[j],     c1 = g_csr_coef[j + 1];
        float c2 = g_csr_coef[j + 2], c3 = g_csr_coef[j + 3];
        float2 v0 = xw2[(size_t)s0 * 128 + fo];
        float2 v1 = xw2[(size_t)s1 * 128 + fo];
        float2 v2 = xw2[(size_t)s2 * 128 + fo];
        float2 v3 = xw2[(size_t)s3 * 128 + fo];
        acc.x += c0 * v0.x + c1 * v1.x + c2 * v2.x + c3 * v3.x;
        acc.y += c0 * v0.y + c1 * v1.y + c2 * v2.y + c3 * v3.y;
    }
    for (; j < end; j++) {
        int s = g_csr_src[j];
        float c = g_csr_coef[j];
        float2 v = xw2[(size_t)s * 128 + fo];
        acc.x += c * v.x;
        acc.y += c * v.y;
    }
    float dis = g_dis[d];
    float d2 = dis * dis;
    float2 sv = xw2[(size_t)d * 128 + fo];
    acc.x += d2 * sv.x + bias[fo * 2];
    acc.y += d2 * sv.y + bias[fo * 2 + 1];
    acc.x = fmaxf(acc.x, 0.f);
    acc.y = fmaxf(acc.y, 0.f);
    if (mode == 1) {
        ((float2*)g_bufB)[(size_t)d * 128 + fo] = acc;
    } else {
        __half2 hv;
        hv.x = __float2half(acc.x);
        hv.y = __float2half(acc.y);
        ((__half2*)g_a16)[(size_t)d * 128 + fo] = hv;
    }
}

// ---------------- segment mean pool (two-phase) ----------------------------
__global__ void k_pool1() {
    int t = blockIdx.x >> 4;
    int p = blockIdx.x & 15;
    int f = threadIdx.x;
    int r0 = p * 98;
    int r1 = r0 + 98; if (r1 > CHUNK) r1 = CHUNK;
    const float* base = g_bufB + ((size_t)t * CHUNK + r0) * D;
    float acc = 0.f;
#pragma unroll 4
    for (int i = 0; i < r1 - r0; i++) acc += base[(size_t)i * D + f];
    g_ppart[t][p][f] = acc;
}
__global__ void k_pool2() {
    int t = blockIdx.x, f = threadIdx.x;
    float acc = 0.f;
#pragma unroll
    for (int p = 0; p < POOL_PARTS; p++) acc += g_ppart[t][p][f];
    g_pooled[t * D + f] = acc * (1.0f / (float)CHUNK);
}

// ---------------- gx = pooled @ w_ih^T + b_ih ------------------------------
__global__ void k_gx(const float* __restrict__ w_ih, const float* __restrict__ b_ih) {
    int idx = blockIdx.x * blockDim.x + threadIdx.x;
    if (idx >= T_STEPS * 3 * D) return;
    int t = idx / (3 * D), j = idx % (3 * D);
    const float4* w = (const float4*)(w_ih + (size_t)j * D);
    const float4* p = (const float4*)(g_pooled + t * D);
    float acc = b_ih[j];
#pragma unroll 4
    for (int k = 0; k < D / 4; k++) {
        float4 a = w[k], b = p[k];
        acc += a.x * b.x + a.y * b.y + a.z * b.z + a.w * b.w;
    }
    g_gx[idx] = acc;
}

// ---------------- distributed GRU ------------------------------------------
__global__ void k_gru_reset() {
    int i = blockIdx.x * blockDim.x + threadIdx.x;
    if (i < (T_STEPS + 2) * GRU_NB) ((volatile int*)g_gru_flag)[i] = 0;
}
__device__ __forceinline__ void gru_barrier(int id, int b, int tid) {
    __syncthreads();
    if (tid == 0) {
        __threadfence();
        g_gru_flag[id][b] = 1;
    }
    if (tid < GRU_NB) {
        while (g_gru_flag[id][tid] == 0) { }
    }
    __syncthreads();
}
__global__ __launch_bounds__(256)
void k_gru(const float* __restrict__ w_hh, const float* __restrict__ b_hh,
           const float* __restrict__ Wc, const float* __restrict__ bc,
           float* __restrict__ out) {
    __shared__ float w_sh[3 * GRU_UPB][D];
    __shared__ float h_sh[D];
    __shared__ float gh_sh[3 * GRU_UPB];
    __shared__ float bhh_sh[3 * GRU_UPB];
    int b = blockIdx.x, tid = threadIdx.x;
    int warp = tid >> 5, lane = tid & 31;

    for (int idx = tid; idx < 3 * GRU_UPB * D; idx += 256) {
        int l = idx >> 8, k = idx & 255;
        int row = (l >> 3) * D + b * GRU_UPB + (l & 7);
        w_sh[l][k] = w_hh[(size_t)row * D + k];
    }
    if (tid < 3 * GRU_UPB) {
        int row = (tid >> 3) * D + b * GRU_UPB + (tid & 7);
        bhh_sh[tid] = b_hh[row];
    }
    if (tid < GRU_UPB) g_h[b * GRU_UPB + tid] = 0.f;
    __threadfence();
    gru_barrier(0, b, tid);

    for (int t = 0; t < T_STEPS; t++) {
        h_sh[tid] = g_h[tid];
        __syncthreads();
#pragma unroll
        for (int rr = 0; rr < 3; rr++) {
            int l = warp * 3 + rr;
            const float4* w = (const float4*)&w_sh[l][lane * 8];
            float4 a0 = w[0], a1 = w[1];
            float4 h0 = *(const float4*)&h_sh[lane * 8];
            float4 h1 = *(const float4*)&h_sh[lane * 8 + 4];
            float p = a0.x * h0.x + a0.y * h0.y + a0.z * h0.z + a0.w * h0.w
                    + a1.x * h1.x + a1.y * h1.y + a1.z * h1.z + a1.w * h1.w;
#pragma unroll
            for (int o = 16; o > 0; o >>= 1) p += __shfl_down_sync(0xffffffffu, p, o);
            if (lane == 0) gh_sh[l] = p + bhh_sh[l];
        }
        __syncthreads();
        if (tid < GRU_UPB) {
            int u = b * GRU_UPB + tid;
            float xr = g_gx[t * 3 * D + u];
            float xz = g_gx[t * 3 * D + D + u];
            float xn = g_gx[t * 3 * D + 2 * D + u];
            float r_ = 1.f / (1.f + expf(-(xr + gh_sh[tid])));
            float z_ = 1.f / (1.f + expf(-(xz + gh_sh[GRU_UPB + tid])));
            float n_ = tanhf(xn + r_ * gh_sh[2 * GRU_UPB + tid]);
            g_h[u] = (1.f - z_) * n_ + z_ * h_sh[u];
        }
        __threadfence();
        gru_barrier(t + 1, b, tid);
    }
    if (b == 0 && tid < D_OUT) {
        float acc = bc[tid];
        for (int k = 0; k < D; k++) acc += Wc[(size_t)tid * D + k] * g_h[k];
        out[tid] = acc;
    }
}

// ---------------- launch ----------------------------------------------------
extern "C" void kernel_launch(void* const* d_in, const int* in_sizes, int n_in,
                              void* d_out, int out_size) {
    int idx_x = 0, idx_ei = 1;
    if (in_sizes[idx_ei] != 2 * N_EDGES) {
        for (int i = 0; i < n_in; i++) if (in_sizes[i] == 2 * N_EDGES) { idx_ei = i; break; }
    }
    if (in_sizes[idx_x] != N_NODES * D) {
        for (int i = 0; i < n_in; i++) if (in_sizes[i] == N_NODES * D) { idx_x = i; break; }
    }

    const float* x    = (const float*)d_in[idx_x];
    const int*   ei   = (const int*)d_in[idx_ei];
    const float* W1   = (const float*)d_in[3];
    const float* b1   = (const float*)d_in[4];
    const float* W2   = (const float*)d_in[5];
    const float* b2   = (const float*)d_in[6];
    const float* w_ih = (const float*)d_in[7];
    const float* w_hh = (const float*)d_in[8];
    const float* b_ih = (const float*)d_in[9];
    const float* b_hh = (const float*)d_in[10];
    const float* Wc   = (const float*)d_in[11];
    const float* bc   = (const float*)d_in[12];
    float* out = (float*)d_out;

    const int* src = ei;
    const int* dst = ei + N_EDGES;

    dim3 gemmGrid(4, (N_NODES + 127) / 128);
    dim3 gcnGrid(N_NODES, 2);

    // Launch order chosen so GEMM1 is launch #5 (ncu -s 5 -c 1 profiles it).
    k_prep_x<<<(N_NODES * 128 + 255) / 256, 256>>>(x);                 // 0
    k_prep_w<<<(D * D + 255) / 256, 256>>>(W1);                        // 1
    k_zero_cnt<<<(N_NODES + 255) / 256, 256>>>();                      // 2
    k_hist<<<(N_EDGES + 255) / 256, 256>>>(dst);                       // 3
    k_scan1<<<NB_SCAN, 256>>>();                                       // 4
    k_gemm_f16<<<gemmGrid, 256>>>(N_NODES);                            // 5  <- profiled
    k_scan2<<<1, 128>>>(NB_SCAN);                                      // 6
    k_scan3<<<(N_NODES + 255) / 256, 256>>>();                         // 7
    k_scatter<<<(N_EDGES + 255) / 256, 256>>>(src, dst);               // 8
    k_gcn<<<gcnGrid, 64>>>(b1, 0);                                     // 9

    k_prep_w<<<(D * D + 255) / 256, 256>>>(W2);                        // 10
    k_gemm_f16<<<gemmGrid, 256>>>(N_NODES);                            // 11
    k_gcn<<<gcnGrid, 64>>>(b2, 1);                                     // 12

    k_pool1<<<T_STEPS * POOL_PARTS, 256>>>();                          // 13
    k_pool2<<<T_STEPS, 256>>>();                                       // 14
    k_gx<<<(T_STEPS * 3 * D + 127) / 128, 128>>>(w_ih, b_ih);          // 15
    k_gru_reset<<<((T_STEPS + 2) * GRU_NB + 255) / 256, 256>>>();      // 16
    k_gru<<<GRU_NB, 256>>>(w_hh, b_hh, Wc, bc, out);                   // 17
}

// round 9
// speedup vs baseline: 1.3758x; 1.0854x over previous
#include <cuda_runtime.h>
#include <cuda_bf16.h>
#include <cuda_fp16.h>
#include <math.h>
#include <stdint.h>

#define N_NODES 100000
#define N_EDGES 1600000
#define T_STEPS 64
#define D 256
#define D_OUT 16
#define CHUNK 1562
#define NB_SCAN 98
#define GRU_NB 32
#define GRU_UPB 8
#define POOL_PARTS 16

// ---------------- scratch ---------------------------------------------------
__device__ __align__(16) int   g_cnt[N_NODES];
__device__ __align__(16) float g_dis[N_NODES];
__device__ __align__(16) int   g_row_ptr[N_NODES + 1];
__device__ __align__(16) int   g_cursor[N_NODES];
__device__ __align__(16) int   g_csr_src[N_EDGES];
__device__ __align__(16) float g_csr_coef[N_EDGES];
__device__ __align__(16) __half g_xw16[(size_t)N_NODES * D];  // GEMM out (fp16)
__device__ __align__(16) float g_bufB[(size_t)N_NODES * D];   // layer-2 GCN out
__device__ __align__(16) __half g_a16[(size_t)N_NODES * D];   // GEMM A (fp16)
__device__ __align__(16) __half g_bh16[D * D];                // W^T hi [N][K]
__device__ __align__(16) __half g_bl16[D * D];                // W^T lo*4096 [N][K]
__device__ __align__(16) float g_pooled[T_STEPS * D];
__device__ __align__(16) float g_ppart[T_STEPS][POOL_PARTS][D];
__device__ __align__(16) float g_gx[T_STEPS * 3 * D];
__device__ __align__(16) int   g_blocksums[128];
__device__ volatile int   g_gru_flag[T_STEPS + 2][GRU_NB];
__device__ volatile float g_h[D];

// ---------------- CSR build ------------------------------------------------
__global__ void k_zero_cnt() {
    int i = blockIdx.x * blockDim.x + threadIdx.x;
    if (i < N_NODES) g_cnt[i] = 0;
}
__global__ void k_hist(const int* __restrict__ dst) {
    int e = blockIdx.x * blockDim.x + threadIdx.x;
    if (e < N_EDGES) {
        int d = dst[e];
        if (d >= 0 && d < N_NODES) atomicAdd(&g_cnt[d], 1);
    }
}
__global__ void k_scan1() {
    __shared__ int sh[256];
    int b = blockIdx.x, tid = threadIdx.x;
    int base = b * 1024;
    int v[4];
#pragma unroll
    for (int i = 0; i < 4; i++) {
        int idx = base + tid * 4 + i;
        v[i] = (idx < N_NODES) ? g_cnt[idx] : 0;
    }
    int s = v[0] + v[1] + v[2] + v[3];
    sh[tid] = s;
    __syncthreads();
    for (int off = 1; off < 256; off <<= 1) {
        int x = (tid >= off) ? sh[tid - off] : 0;
        __syncthreads();
        sh[tid] += x;
        __syncthreads();
    }
    int excl = sh[tid] - s;
    if (tid == 255) g_blocksums[b] = sh[255];
    int run = excl;
#pragma unroll
    for (int i = 0; i < 4; i++) {
        int idx = base + tid * 4 + i;
        if (idx < N_NODES) g_row_ptr[idx] = run;
        run += v[i];
    }
}
__global__ void k_scan2(int nb) {
    __shared__ int sh[128];
    int tid = threadIdx.x;
    int s = (tid < nb) ? g_blocksums[tid] : 0;
    sh[tid] = s;
    __syncthreads();
    for (int off = 1; off < 128; off <<= 1) {
        int x = (tid >= off) ? sh[tid - off] : 0;
        __syncthreads();
        sh[tid] += x;
        __syncthreads();
    }
    if (tid < nb) g_blocksums[tid] = sh[tid] - s;
}
__global__ void k_scan3() {
    int i = blockIdx.x * blockDim.x + threadIdx.x;
    if (i < N_NODES) {
        int v = g_row_ptr[i] + g_blocksums[i >> 10];
        g_row_ptr[i] = v;
        g_cursor[i]  = v;
        g_dis[i] = rsqrtf((float)g_cnt[i] + 1.0f);
    }
    if (i == 0) g_row_ptr[N_NODES] = N_EDGES;
}
__global__ void k_scatter(const int* __restrict__ src, const int* __restrict__ dst) {
    int e = blockIdx.x * blockDim.x + threadIdx.x;
    if (e < N_EDGES) {
        int s = src[e], d = dst[e];
        if (s < 0 || s >= N_NODES || d < 0 || d >= N_NODES) return;
        int p = atomicAdd(&g_cursor[d], 1);
        g_csr_src[p]  = s;
        g_csr_coef[p] = g_dis[s] * g_dis[d];
    }
}

// ---------------- input prep -----------------------------------------------
__global__ void k_prep_x(const float* __restrict__ x) {
    int i = blockIdx.x * blockDim.x + threadIdx.x;   // float2 index
    if (i >= N_NODES * 128) return;
    float2 v = ((const float2*)x)[i];
    __half2 h;
    h.x = __float2half(v.x);
    h.y = __float2half(v.y);
    ((__half2*)g_a16)[i] = h;
}
// W [K,N] row-major -> W^T [N][K]; hi fp16, lo = (w-hi)*4096 fp16
__global__ void k_prep_w(const float* __restrict__ W) {
    int idx = blockIdx.x * blockDim.x + threadIdx.x;  // n*256 + k
    if (idx >= D * D) return;
    int n = idx >> 8, k = idx & 255;
    float w = W[k * D + n];
    __half hi = __float2half(w);
    float resid = (w - __half2float(hi)) * 4096.0f;
    g_bh16[idx] = hi;
    g_bl16[idx] = __float2half(resid);
}

// ---------------- fp16 2-pass tensor GEMM (A single, W split) ---------------
// block 128(M) x 64(N), 8 warps = 4Mx2N, warp tile 32x32, BK=32.
// C = A·Whi + (A·Wlo)*2^-12, dual fp32 accumulators -> fp16 output.
#define APITCH 40

__device__ __forceinline__ void mma_f16(float* c, const uint32_t* a, const uint32_t* b) {
    asm volatile(
        "mma.sync.aligned.m16n8k16.row.col.f32.f16.f16.f32 "
        "{%0,%1,%2,%3}, {%4,%5,%6,%7}, {%8,%9}, {%0,%1,%2,%3};"
        : "+f"(c[0]), "+f"(c[1]), "+f"(c[2]), "+f"(c[3])
        : "r"(a[0]), "r"(a[1]), "r"(a[2]), "r"(a[3]), "r"(b[0]), "r"(b[1]));
}

__global__ __launch_bounds__(256)
void k_gemm_f16(int M) {
    __shared__ __half Ah[128][APITCH];
    __shared__ __half Bh[64][APITCH];
    __shared__ __half Bl[64][APITCH];

    int bm = blockIdx.y * 128;
    int bn = blockIdx.x * 64;
    int tid  = threadIdx.x;
    int warp = tid >> 5, lane = tid & 31;
    int wm = warp & 3;
    int wn = warp >> 2;
    int lq = lane >> 2;
    int lr = lane & 3;

    float accM[2][4][4], accC[2][4][4];
#pragma unroll
    for (int i = 0; i < 2; i++)
#pragma unroll
        for (int j = 0; j < 4; j++)
#pragma unroll
            for (int v = 0; v < 4; v++) { accM[i][j][v] = 0.f; accC[i][j][v] = 0.f; }

    for (int ch = 0; ch < 8; ch++) {
        int k0 = ch * 32;
#pragma unroll
        for (int i = 0; i < 2; i++) {
            int idx = tid + 256 * i;
            int row = idx >> 2, c = idx & 3;
            uint4 v = make_uint4(0, 0, 0, 0);
            if (bm + row < M)
                v = *(const uint4*)(g_a16 + (size_t)(bm + row) * D + k0 + c * 8);
            *(uint4*)&Ah[row][c * 8] = v;
        }
        {
            int row = tid >> 2, c = tid & 3;
            size_t g = (size_t)(bn + row) * D + k0 + c * 8;
            *(uint4*)&Bh[row][c * 8] = *(const uint4*)(g_bh16 + g);
            *(uint4*)&Bl[row][c * 8] = *(const uint4*)(g_bl16 + g);
        }
        __syncthreads();

#pragma unroll
        for (int ks = 0; ks < 2; ks++) {
            int kk = ks * 16;
            uint32_t a[2][4], bH[4][2], bL[4][2];
#pragma unroll
            for (int mt = 0; mt < 2; mt++) {
                int r = wm * 32 + mt * 16 + lq;
                a[mt][0] = *(const uint32_t*)&Ah[r    ][kk + lr * 2];
                a[mt][1] = *(const uint32_t*)&Ah[r + 8][kk + lr * 2];
                a[mt][2] = *(const uint32_t*)&Ah[r    ][kk + 8 + lr * 2];
                a[mt][3] = *(const uint32_t*)&Ah[r + 8][kk + 8 + lr * 2];
            }
#pragma unroll
            for (int nt = 0; nt < 4; nt++) {
                int n = wn * 32 + nt * 8 + lq;
                bH[nt][0] = *(const uint32_t*)&Bh[n][kk + lr * 2];
                bH[nt][1] = *(const uint32_t*)&Bh[n][kk + 8 + lr * 2];
                bL[nt][0] = *(const uint32_t*)&Bl[n][kk + lr * 2];
                bL[nt][1] = *(const uint32_t*)&Bl[n][kk + 8 + lr * 2];
            }
#pragma unroll
            for (int mt = 0; mt < 2; mt++)
#pragma unroll
                for (int nt = 0; nt < 4; nt++) {
                    mma_f16(accM[mt][nt], a[mt], bH[nt]);
                    mma_f16(accC[mt][nt], a[mt], bL[nt]);
                }
        }
        __syncthreads();
    }

    const float s = 1.0f / 4096.0f;
#pragma unroll
    for (int mt = 0; mt < 2; mt++) {
#pragma unroll
        for (int nt = 0; nt < 4; nt++) {
            int gr0 = bm + wm * 32 + mt * 16 + lq;
            int gc  = bn + wn * 32 + nt * 8 + lr * 2;
            __half2 h0, h1;
            h0.x = __float2half(accM[mt][nt][0] + accC[mt][nt][0] * s);
            h0.y = __float2half(accM[mt][nt][1] + accC[mt][nt][1] * s);
            h1.x = __float2half(accM[mt][nt][2] + accC[mt][nt][2] * s);
            h1.y = __float2half(accM[mt][nt][3] + accC[mt][nt][3] * s);
            if (gr0 < M)
                *(__half2*)(g_xw16 + (size_t)gr0 * D + gc) = h0;
            if (gr0 + 8 < M)
                *(__half2*)(g_xw16 + (size_t)(gr0 + 8) * D + gc) = h1;
        }
    }
}

// ---------------- fused GCN aggregation (fp16 rows, single pass) ------------
// one block (128 threads) per dst node; full 51MB working set L2-resident.
// mode 0: emit fp16 (feeds next GEMM). mode 1: fp32 -> g_bufB.
__global__ __launch_bounds__(128)
void k_gcn(const float* __restrict__ bias, int mode) {
    int d   = blockIdx.x;
    int tid = threadIdx.x;      // half2 index within row (128 x 2 feats)
    int beg = g_row_ptr[d], end = g_row_ptr[d + 1];
    const __half2* xw = (const __half2*)g_xw16;
    float2 acc = make_float2(0.f, 0.f);
    int j = beg;
    for (; j + 3 < end; j += 4) {
        int s0 = g_csr_src[j],     s1 = g_csr_src[j + 1];
        int s2 = g_csr_src[j + 2], s3 = g_csr_src[j + 3];
        float c0 = g_csr_coef[j],     c1 = g_csr_coef[j + 1];
        float c2 = g_csr_coef[j + 2], c3 = g_csr_coef[j + 3];
        float2 v0 = __half22float2(xw[(size_t)s0 * 128 + tid]);
        float2 v1 = __half22float2(xw[(size_t)s1 * 128 + tid]);
        float2 v2 = __half22float2(xw[(size_t)s2 * 128 + tid]);
        float2 v3 = __half22float2(xw[(size_t)s3 * 128 + tid]);
        acc.x += c0 * v0.x + c1 * v1.x + c2 * v2.x + c3 * v3.x;
        acc.y += c0 * v0.y + c1 * v1.y + c2 * v2.y + c3 * v3.y;
    }
    for (; j < end; j++) {
        int s = g_csr_src[j];
        float c = g_csr_coef[j];
        float2 v = __half22float2(xw[(size_t)s * 128 + tid]);
        acc.x += c * v.x;
        acc.y += c * v.y;
    }
    float dis = g_dis[d];
    float d2 = dis * dis;
    float2 sv = __half22float2(xw[(size_t)d * 128 + tid]);
    acc.x += d2 * sv.x + bias[tid * 2];
    acc.y += d2 * sv.y + bias[tid * 2 + 1];
    acc.x = fmaxf(acc.x, 0.f);
    acc.y = fmaxf(acc.y, 0.f);
    if (mode == 1) {
        ((float2*)g_bufB)[(size_t)d * 128 + tid] = acc;
    } else {
        __half2 hv;
        hv.x = __float2half(acc.x);
        hv.y = __float2half(acc.y);
        ((__half2*)g_a16)[(size_t)d * 128 + tid] = hv;
    }
}

// ---------------- segment mean pool (two-phase) ----------------------------
__global__ void k_pool1() {
    int t = blockIdx.x >> 4;
    int p = blockIdx.x & 15;
    int f = threadIdx.x;
    int r0 = p * 98;
    int r1 = r0 + 98; if (r1 > CHUNK) r1 = CHUNK;
    const float* base = g_bufB + ((size_t)t * CHUNK + r0) * D;
    float acc = 0.f;
#pragma unroll 4
    for (int i = 0; i < r1 - r0; i++) acc += base[(size_t)i * D + f];
    g_ppart[t][p][f] = acc;
}
__global__ void k_pool2() {
    int t = blockIdx.x, f = threadIdx.x;
    float acc = 0.f;
#pragma unroll
    for (int p = 0; p < POOL_PARTS; p++) acc += g_ppart[t][p][f];
    g_pooled[t * D + f] = acc * (1.0f / (float)CHUNK);
}

// ---------------- gx = pooled @ w_ih^T + b_ih ------------------------------
__global__ void k_gx(const float* __restrict__ w_ih, const float* __restrict__ b_ih) {
    int idx = blockIdx.x * blockDim.x + threadIdx.x;
    if (idx >= T_STEPS * 3 * D) return;
    int t = idx / (3 * D), j = idx % (3 * D);
    const float4* w = (const float4*)(w_ih + (size_t)j * D);
    const float4* p = (const float4*)(g_pooled + t * D);
    float acc = b_ih[j];
#pragma unroll 4
    for (int k = 0; k < D / 4; k++) {
        float4 a = w[k], b = p[k];
        acc += a.x * b.x + a.y * b.y + a.z * b.z + a.w * b.w;
    }
    g_gx[idx] = acc;
}

// ---------------- distributed GRU ------------------------------------------
__global__ void k_gru_reset() {
    int i = blockIdx.x * blockDim.x + threadIdx.x;
    if (i < (T_STEPS + 2) * GRU_NB) ((volatile int*)g_gru_flag)[i] = 0;
}
__device__ __forceinline__ void gru_barrier(int id, int b, int tid) {
    __syncthreads();
    if (tid == 0) {
        __threadfence();
        g_gru_flag[id][b] = 1;
    }
    if (tid < GRU_NB) {
        while (g_gru_flag[id][tid] == 0) { }
    }
    __syncthreads();
}
__global__ __launch_bounds__(256)
void k_gru(const float* __restrict__ w_hh, const float* __restrict__ b_hh,
           const float* __restrict__ Wc, const float* __restrict__ bc,
           float* __restrict__ out) {
    __shared__ float w_sh[3 * GRU_UPB][D];
    __shared__ float h_sh[D];
    __shared__ float gh_sh[3 * GRU_UPB];
    __shared__ float bhh_sh[3 * GRU_UPB];
    int b = blockIdx.x, tid = threadIdx.x;
    int warp = tid >> 5, lane = tid & 31;

    for (int idx = tid; idx < 3 * GRU_UPB * D; idx += 256) {
        int l = idx >> 8, k = idx & 255;
        int row = (l >> 3) * D + b * GRU_UPB + (l & 7);
        w_sh[l][k] = w_hh[(size_t)row * D + k];
    }
    if (tid < 3 * GRU_UPB) {
        int row = (tid >> 3) * D + b * GRU_UPB + (tid & 7);
        bhh_sh[tid] = b_hh[row];
    }
    if (tid < GRU_UPB) g_h[b * GRU_UPB + tid] = 0.f;
    __threadfence();
    gru_barrier(0, b, tid);

    for (int t = 0; t < T_STEPS; t++) {
        h_sh[tid] = g_h[tid];
        __syncthreads();
#pragma unroll
        for (int rr = 0; rr < 3; rr++) {
            int l = warp * 3 + rr;
            const float4* w = (const float4*)&w_sh[l][lane * 8];
            float4 a0 = w[0], a1 = w[1];
            float4 h0 = *(const float4*)&h_sh[lane * 8];
            float4 h1 = *(const float4*)&h_sh[lane * 8 + 4];
            float p = a0.x * h0.x + a0.y * h0.y + a0.z * h0.z + a0.w * h0.w
                    + a1.x * h1.x + a1.y * h1.y + a1.z * h1.z + a1.w * h1.w;
#pragma unroll
            for (int o = 16; o > 0; o >>= 1) p += __shfl_down_sync(0xffffffffu, p, o);
            if (lane == 0) gh_sh[l] = p + bhh_sh[l];
        }
        __syncthreads();
        if (tid < GRU_UPB) {
            int u = b * GRU_UPB + tid;
            float xr = g_gx[t * 3 * D + u];
            float xz = g_gx[t * 3 * D + D + u];
            float xn = g_gx[t * 3 * D + 2 * D + u];
            float r_ = 1.f / (1.f + expf(-(xr + gh_sh[tid])));
            float z_ = 1.f / (1.f + expf(-(xz + gh_sh[GRU_UPB + tid])));
            float n_ = tanhf(xn + r_ * gh_sh[2 * GRU_UPB + tid]);
            g_h[u] = (1.f - z_) * n_ + z_ * h_sh[u];
        }
        __threadfence();
        gru_barrier(t + 1, b, tid);
    }
    if (b == 0 && tid < D_OUT) {
        float acc = bc[tid];
        for (int k = 0; k < D; k++) acc += Wc[(size_t)tid * D + k] * g_h[k];
        out[tid] = acc;
    }
}

// ---------------- launch ----------------------------------------------------
extern "C" void kernel_launch(void* const* d_in, const int* in_sizes, int n_in,
                              void* d_out, int out_size) {
    int idx_x = 0, idx_ei = 1;
    if (in_sizes[idx_ei] != 2 * N_EDGES) {
        for (int i = 0; i < n_in; i++) if (in_sizes[i] == 2 * N_EDGES) { idx_ei = i; break; }
    }
    if (in_sizes[idx_x] != N_NODES * D) {
        for (int i = 0; i < n_in; i++) if (in_sizes[i] == N_NODES * D) { idx_x = i; break; }
    }

    const float* x    = (const float*)d_in[idx_x];
    const int*   ei   = (const int*)d_in[idx_ei];
    const float* W1   = (const float*)d_in[3];
    const float* b1   = (const float*)d_in[4];
    const float* W2   = (const float*)d_in[5];
    const float* b2   = (const float*)d_in[6];
    const float* w_ih = (const float*)d_in[7];
    const float* w_hh = (const float*)d_in[8];
    const float* b_ih = (const float*)d_in[9];
    const float* b_hh = (const float*)d_in[10];
    const float* Wc   = (const float*)d_in[11];
    const float* bc   = (const float*)d_in[12];
    float* out = (float*)d_out;

    const int* src = ei;
    const int* dst = ei + N_EDGES;

    dim3 gemmGrid(4, (N_NODES + 127) / 128);

    // Launch order keeps GEMM1 at index 5, and puts gather1 at a fixed slot.
    k_prep_x<<<(N_NODES * 128 + 255) / 256, 256>>>(x);                 // 0
    k_prep_w<<<(D * D + 255) / 256, 256>>>(W1);                        // 1
    k_zero_cnt<<<(N_NODES + 255) / 256, 256>>>();                      // 2
    k_hist<<<(N_EDGES + 255) / 256, 256>>>(dst);                       // 3
    k_scan1<<<NB_SCAN, 256>>>();                                       // 4
    k_gemm_f16<<<gemmGrid, 256>>>(N_NODES);                            // 5
    k_scan2<<<1, 128>>>(NB_SCAN);                                      // 6
    k_scan3<<<(N_NODES + 255) / 256, 256>>>();                         // 7
    k_scatter<<<(N_EDGES + 255) / 256, 256>>>(src, dst);               // 8
    k_gcn<<<N_NODES, 128>>>(b1, 0);                                    // 9

    k_prep_w<<<(D * D + 255) / 256, 256>>>(W2);                        // 10
    k_gemm_f16<<<gemmGrid, 256>>>(N_NODES);                            // 11
    k_gcn<<<N_NODES, 128>>>(b2, 1);                                    // 12

    k_pool1<<<T_STEPS * POOL_PARTS, 256>>>();                          // 13
    k_pool2<<<T_STEPS, 256>>>();                                       // 14
    k_gx<<<(T_STEPS * 3 * D + 127) / 128, 128>>>(w_ih, b_ih);          // 15
    k_gru_reset<<<((T_STEPS + 2) * GRU_NB + 255) / 256, 256>>>();      // 16
    k_gru<<<GRU_NB, 256>>>(w_hh, b_hh, Wc, bc, out);                   // 17
}

// round 11
// speedup vs baseline: 1.5475x; 1.1248x over previous
#include <cuda_runtime.h>
#include <cuda_bf16.h>
#include <cuda_fp16.h>
#include <math.h>
#include <stdint.h>

#define N_NODES 100000
#define N_EDGES 1600000
#define T_STEPS 64
#define D 256
#define D_OUT 16
#define CHUNK 1562
#define NB_SCAN 98
#define GRU_NB 32
#define GRU_UPB 8
#define POOL_PARTS 16

// ---------------- scratch ---------------------------------------------------
__device__ __align__(16) int   g_cnt[N_NODES];
__device__ __align__(16) float g_dis[N_NODES];
__device__ __align__(16) int   g_row_ptr[N_NODES + 1];
__device__ __align__(16) int   g_cursor[N_NODES];
__device__ __align__(16) int   g_csr_src[N_EDGES];
__device__ __align__(16) float g_csr_coef[N_EDGES];
__device__ __align__(16) __half g_xw16[(size_t)N_NODES * D];  // GEMM out (fp16)
__device__ __align__(16) float g_bufB[(size_t)N_NODES * D];   // layer-2 GCN out
__device__ __align__(16) __half g_a16[(size_t)N_NODES * D];   // GEMM A (fp16)
__device__ __align__(16) __half g_bh16[D * D];                // W^T [N][K] fp16
__device__ __align__(16) float g_pooled[T_STEPS * D];
__device__ __align__(16) float g_ppart[T_STEPS][POOL_PARTS][D];
__device__ __align__(16) float g_gx[T_STEPS * 3 * D];
__device__ __align__(16) int   g_blocksums[128];
__device__ volatile int   g_gru_flag[T_STEPS + 2][GRU_NB];
__device__ volatile float g_h[D];

// ---------------- CSR build ------------------------------------------------
__global__ void k_zero_cnt() {
    int i = blockIdx.x * blockDim.x + threadIdx.x;
    if (i < N_NODES) g_cnt[i] = 0;
}
__global__ void k_hist(const int* __restrict__ dst) {
    int e = blockIdx.x * blockDim.x + threadIdx.x;
    if (e < N_EDGES) {
        int d = dst[e];
        if (d >= 0 && d < N_NODES) atomicAdd(&g_cnt[d], 1);
    }
}
__global__ void k_scan1() {
    __shared__ int sh[256];
    int b = blockIdx.x, tid = threadIdx.x;
    int base = b * 1024;
    int v[4];
#pragma unroll
    for (int i = 0; i < 4; i++) {
        int idx = base + tid * 4 + i;
        v[i] = (idx < N_NODES) ? g_cnt[idx] : 0;
    }
    int s = v[0] + v[1] + v[2] + v[3];
    sh[tid] = s;
    __syncthreads();
    for (int off = 1; off < 256; off <<= 1) {
        int x = (tid >= off) ? sh[tid - off] : 0;
        __syncthreads();
        sh[tid] += x;
        __syncthreads();
    }
    int excl = sh[tid] - s;
    if (tid == 255) g_blocksums[b] = sh[255];
    int run = excl;
#pragma unroll
    for (int i = 0; i < 4; i++) {
        int idx = base + tid * 4 + i;
        if (idx < N_NODES) g_row_ptr[idx] = run;
        run += v[i];
    }
}
__global__ void k_scan2(int nb) {
    __shared__ int sh[128];
    int tid = threadIdx.x;
    int s = (tid < nb) ? g_blocksums[tid] : 0;
    sh[tid] = s;
    __syncthreads();
    for (int off = 1; off < 128; off <<= 1) {
        int x = (tid >= off) ? sh[tid - off] : 0;
        __syncthreads();
        sh[tid] += x;
        __syncthreads();
    }
    if (tid < nb) g_blocksums[tid] = sh[tid] - s;
}
__global__ void k_scan3() {
    int i = blockIdx.x * blockDim.x + threadIdx.x;
    if (i < N_NODES) {
        int v = g_row_ptr[i] + g_blocksums[i >> 10];
        g_row_ptr[i] = v;
        g_cursor[i]  = v;
        g_dis[i] = rsqrtf((float)g_cnt[i] + 1.0f);
    }
    if (i == 0) g_row_ptr[N_NODES] = N_EDGES;
}
__global__ void k_scatter(const int* __restrict__ src, const int* __restrict__ dst) {
    int e = blockIdx.x * blockDim.x + threadIdx.x;
    if (e < N_EDGES) {
        int s = src[e], d = dst[e];
        if (s < 0 || s >= N_NODES || d < 0 || d >= N_NODES) return;
        int p = atomicAdd(&g_cursor[d], 1);
        g_csr_src[p]  = s;
        g_csr_coef[p] = g_dis[s] * g_dis[d];
    }
}

// ---------------- input prep -----------------------------------------------
__global__ void k_prep_x(const float* __restrict__ x) {
    int i = blockIdx.x * blockDim.x + threadIdx.x;   // float2 index
    if (i >= N_NODES * 128) return;
    float2 v = ((const float2*)x)[i];
    __half2 h;
    h.x = __float2half(v.x);
    h.y = __float2half(v.y);
    ((__half2*)g_a16)[i] = h;
}
// W [K,N] row-major -> W^T [N][K] fp16
__global__ void k_prep_w(const float* __restrict__ W) {
    int idx = blockIdx.x * blockDim.x + threadIdx.x;  // n*256 + k
    if (idx >= D * D) return;
    int n = idx >> 8, k = idx & 255;
    g_bh16[idx] = __float2half(W[k * D + n]);
}

// ---------------- fp16 single-pass tensor GEMM ------------------------------
// block 128(M) x 64(N), 8 warps = 4Mx2N, warp tile 32x32, BK=32.
#define APITCH 40

__device__ __forceinline__ void mma_f16(float* c, const uint32_t* a, const uint32_t* b) {
    asm volatile(
        "mma.sync.aligned.m16n8k16.row.col.f32.f16.f16.f32 "
        "{%0,%1,%2,%3}, {%4,%5,%6,%7}, {%8,%9}, {%0,%1,%2,%3};"
        : "+f"(c[0]), "+f"(c[1]), "+f"(c[2]), "+f"(c[3])
        : "r"(a[0]), "r"(a[1]), "r"(a[2]), "r"(a[3]), "r"(b[0]), "r"(b[1]));
}

__global__ __launch_bounds__(256)
void k_gemm_f16(int M) {
    __shared__ __half Ah[128][APITCH];
    __shared__ __half Bh[64][APITCH];

    int bm = blockIdx.y * 128;
    int bn = blockIdx.x * 64;
    int tid  = threadIdx.x;
    int warp = tid >> 5, lane = tid & 31;
    int wm = warp & 3;
    int wn = warp >> 2;
    int lq = lane >> 2;
    int lr = lane & 3;

    float accM[2][4][4];
#pragma unroll
    for (int i = 0; i < 2; i++)
#pragma unroll
        for (int j = 0; j < 4; j++)
#pragma unroll
            for (int v = 0; v < 4; v++) accM[i][j][v] = 0.f;

    for (int ch = 0; ch < 8; ch++) {
        int k0 = ch * 32;
#pragma unroll
        for (int i = 0; i < 2; i++) {
            int idx = tid + 256 * i;
            int row = idx >> 2, c = idx & 3;
            uint4 v = make_uint4(0, 0, 0, 0);
            if (bm + row < M)
                v = *(const uint4*)(g_a16 + (size_t)(bm + row) * D + k0 + c * 8);
            *(uint4*)&Ah[row][c * 8] = v;
        }
        {
            int row = tid >> 2, c = tid & 3;
            size_t g = (size_t)(bn + row) * D + k0 + c * 8;
            *(uint4*)&Bh[row][c * 8] = *(const uint4*)(g_bh16 + g);
        }
        __syncthreads();

#pragma unroll
        for (int ks = 0; ks < 2; ks++) {
            int kk = ks * 16;
            uint32_t a[2][4], bH[4][2];
#pragma unroll
            for (int mt = 0; mt < 2; mt++) {
                int r = wm * 32 + mt * 16 + lq;
                a[mt][0] = *(const uint32_t*)&Ah[r    ][kk + lr * 2];
                a[mt][1] = *(const uint32_t*)&Ah[r + 8][kk + lr * 2];
                a[mt][2] = *(const uint32_t*)&Ah[r    ][kk + 8 + lr * 2];
                a[mt][3] = *(const uint32_t*)&Ah[r + 8][kk + 8 + lr * 2];
            }
#pragma unroll
            for (int nt = 0; nt < 4; nt++) {
                int n = wn * 32 + nt * 8 + lq;
                bH[nt][0] = *(const uint32_t*)&Bh[n][kk + lr * 2];
                bH[nt][1] = *(const uint32_t*)&Bh[n][kk + 8 + lr * 2];
            }
#pragma unroll
            for (int mt = 0; mt < 2; mt++)
#pragma unroll
                for (int nt = 0; nt < 4; nt++)
                    mma_f16(accM[mt][nt], a[mt], bH[nt]);
        }
        __syncthreads();
    }

#pragma unroll
    for (int mt = 0; mt < 2; mt++) {
#pragma unroll
        for (int nt = 0; nt < 4; nt++) {
            int gr0 = bm + wm * 32 + mt * 16 + lq;
            int gc  = bn + wn * 32 + nt * 8 + lr * 2;
            __half2 h0, h1;
            h0.x = __float2half(accM[mt][nt][0]);
            h0.y = __float2half(accM[mt][nt][1]);
            h1.x = __float2half(accM[mt][nt][2]);
            h1.y = __float2half(accM[mt][nt][3]);
            if (gr0 < M)
                *(__half2*)(g_xw16 + (size_t)gr0 * D + gc) = h0;
            if (gr0 + 8 < M)
                *(__half2*)(g_xw16 + (size_t)(gr0 + 8) * D + gc) = h1;
        }
    }
}

// ---------------- fused GCN aggregation (fp16 rows, single pass) ------------
__global__ __launch_bounds__(128)
void k_gcn(const float* __restrict__ bias, int mode) {
    int d   = blockIdx.x;
    int tid = threadIdx.x;
    int beg = g_row_ptr[d], end = g_row_ptr[d + 1];
    const __half2* xw = (const __half2*)g_xw16;
    float2 acc = make_float2(0.f, 0.f);
    int j = beg;
    for (; j + 3 < end; j += 4) {
        int s0 = g_csr_src[j],     s1 = g_csr_src[j + 1];
        int s2 = g_csr_src[j + 2], s3 = g_csr_src[j + 3];
        float c0 = g_csr_coef[j],     c1 = g_csr_coef[j + 1];
        float c2 = g_csr_coef[j + 2], c3 = g_csr_coef[j + 3];
        float2 v0 = __half22float2(xw[(size_t)s0 * 128 + tid]);
        float2 v1 = __half22float2(xw[(size_t)s1 * 128 + tid]);
        float2 v2 = __half22float2(xw[(size_t)s2 * 128 + tid]);
        float2 v3 = __half22float2(xw[(size_t)s3 * 128 + tid]);
        acc.x += c0 * v0.x + c1 * v1.x + c2 * v2.x + c3 * v3.x;
        acc.y += c0 * v0.y + c1 * v1.y + c2 * v2.y + c3 * v3.y;
    }
    for (; j < end; j++) {
        int s = g_csr_src[j];
        float c = g_csr_coef[j];
        float2 v = __half22float2(xw[(size_t)s * 128 + tid]);
        acc.x += c * v.x;
        acc.y += c * v.y;
    }
    float dis = g_dis[d];
    float d2 = dis * dis;
    float2 sv = __half22float2(xw[(size_t)d * 128 + tid]);
    acc.x += d2 * sv.x + bias[tid * 2];
    acc.y += d2 * sv.y + bias[tid * 2 + 1];
    acc.x = fmaxf(acc.x, 0.f);
    acc.y = fmaxf(acc.y, 0.f);
    if (mode == 1) {
        ((float2*)g_bufB)[(size_t)d * 128 + tid] = acc;
    } else {
        __half2 hv;
        hv.x = __float2half(acc.x);
        hv.y = __float2half(acc.y);
        ((__half2*)g_a16)[(size_t)d * 128 + tid] = hv;
    }
}

// ---------------- segment mean pool (two-phase) ----------------------------
__global__ void k_pool1() {
    int t = blockIdx.x >> 4;
    int p = blockIdx.x & 15;
    int f = threadIdx.x;
    int r0 = p * 98;
    int r1 = r0 + 98; if (r1 > CHUNK) r1 = CHUNK;
    const float* base = g_bufB + ((size_t)t * CHUNK + r0) * D;
    float acc = 0.f;
#pragma unroll 4
    for (int i = 0; i < r1 - r0; i++) acc += base[(size_t)i * D + f];
    g_ppart[t][p][f] = acc;
}
__global__ void k_pool2() {
    int t = blockIdx.x, f = threadIdx.x;
    float acc = 0.f;
#pragma unroll
    for (int p = 0; p < POOL_PARTS; p++) acc += g_ppart[t][p][f];
    g_pooled[t * D + f] = acc * (1.0f / (float)CHUNK);
}

// ---------------- gx = pooled @ w_ih^T + b_ih ------------------------------
__global__ void k_gx(const float* __restrict__ w_ih, const float* __restrict__ b_ih) {
    int idx = blockIdx.x * blockDim.x + threadIdx.x;
    if (idx >= T_STEPS * 3 * D) return;
    int t = idx / (3 * D), j = idx % (3 * D);
    const float4* w = (const float4*)(w_ih + (size_t)j * D);
    const float4* p = (const float4*)(g_pooled + t * D);
    float acc = b_ih[j];
#pragma unroll 4
    for (int k = 0; k < D / 4; k++) {
        float4 a = w[k], b = p[k];
        acc += a.x * b.x + a.y * b.y + a.z * b.z + a.w * b.w;
    }
    g_gx[idx] = acc;
}

// ---------------- distributed GRU ------------------------------------------
__global__ void k_gru_reset() {
    int i = blockIdx.x * blockDim.x + threadIdx.x;
    if (i < (T_STEPS + 2) * GRU_NB) ((volatile int*)g_gru_flag)[i] = 0;
}
__device__ __forceinline__ void gru_barrier(int id, int b, int tid) {
    __syncthreads();
    if (tid == 0) {
        __threadfence();
        g_gru_flag[id][b] = 1;
    }
    if (tid < GRU_NB) {
        while (g_gru_flag[id][tid] == 0) { }
    }
    __syncthreads();
}
__global__ __launch_bounds__(256)
void k_gru(const float* __restrict__ w_hh, const float* __restrict__ b_hh,
           const float* __restrict__ Wc, const float* __restrict__ bc,
           float* __restrict__ out) {
    __shared__ float w_sh[3 * GRU_UPB][D];
    __shared__ float h_sh[D];
    __shared__ float gh_sh[3 * GRU_UPB];
    __shared__ float bhh_sh[3 * GRU_UPB];
    int b = blockIdx.x, tid = threadIdx.x;
    int warp = tid >> 5, lane = tid & 31;

    for (int idx = tid; idx < 3 * GRU_UPB * D; idx += 256) {
        int l = idx >> 8, k = idx & 255;
        int row = (l >> 3) * D + b * GRU_UPB + (l & 7);
        w_sh[l][k] = w_hh[(size_t)row * D + k];
    }
    if (tid < 3 * GRU_UPB) {
        int row = (tid >> 3) * D + b * GRU_UPB + (tid & 7);
        bhh_sh[tid] = b_hh[row];
    }
    if (tid < GRU_UPB) g_h[b * GRU_UPB + tid] = 0.f;
    __threadfence();
    gru_barrier(0, b, tid);

    for (int t = 0; t < T_STEPS; t++) {
        h_sh[tid] = g_h[tid];
        __syncthreads();
#pragma unroll
        for (int rr = 0; rr < 3; rr++) {
            int l = warp * 3 + rr;
            const float4* w = (const float4*)&w_sh[l][lane * 8];
            float4 a0 = w[0], a1 = w[1];
            float4 h0 = *(const float4*)&h_sh[lane * 8];
            float4 h1 = *(const float4*)&h_sh[lane * 8 + 4];
            float p = a0.x * h0.x + a0.y * h0.y + a0.z * h0.z + a0.w * h0.w
                    + a1.x * h1.x + a1.y * h1.y + a1.z * h1.z + a1.w * h1.w;
#pragma unroll
            for (int o = 16; o > 0; o >>= 1) p += __shfl_down_sync(0xffffffffu, p, o);
            if (lane == 0) gh_sh[l] = p + bhh_sh[l];
        }
        __syncthreads();
        if (tid < GRU_UPB) {
            int u = b * GRU_UPB + tid;
            float xr = g_gx[t * 3 * D + u];
            float xz = g_gx[t * 3 * D + D + u];
            float xn = g_gx[t * 3 * D + 2 * D + u];
            float r_ = 1.f / (1.f + expf(-(xr + gh_sh[tid])));
            float z_ = 1.f / (1.f + expf(-(xz + gh_sh[GRU_UPB + tid])));
            float n_ = tanhf(xn + r_ * gh_sh[2 * GRU_UPB + tid]);
            g_h[u] = (1.f - z_) * n_ + z_ * h_sh[u];
        }
        __threadfence();
        gru_barrier(t + 1, b, tid);
    }
    if (b == 0 && tid < D_OUT) {
        float acc = bc[tid];
        for (int k = 0; k < D; k++) acc += Wc[(size_t)tid * D + k] * g_h[k];
        out[tid] = acc;
    }
}

// ---------------- launch ----------------------------------------------------
extern "C" void kernel_launch(void* const* d_in, const int* in_sizes, int n_in,
                              void* d_out, int out_size) {
    int idx_x = 0, idx_ei = 1;
    if (in_sizes[idx_ei] != 2 * N_EDGES) {
        for (int i = 0; i < n_in; i++) if (in_sizes[i] == 2 * N_EDGES) { idx_ei = i; break; }
    }
    if (in_sizes[idx_x] != N_NODES * D) {
        for (int i = 0; i < n_in; i++) if (in_sizes[i] == N_NODES * D) { idx_x = i; break; }
    }

    const float* x    = (const float*)d_in[idx_x];
    const int*   ei   = (const int*)d_in[idx_ei];
    const float* W1   = (const float*)d_in[3];
    const float* b1   = (const float*)d_in[4];
    const float* W2   = (const float*)d_in[5];
    const float* b2   = (const float*)d_in[6];
    const float* w_ih = (const float*)d_in[7];
    const float* w_hh = (const float*)d_in[8];
    const float* b_ih = (const float*)d_in[9];
    const float* b_hh = (const float*)d_in[10];
    const float* Wc   = (const float*)d_in[11];
    const float* bc   = (const float*)d_in[12];
    float* out = (float*)d_out;

    const int* src = ei;
    const int* dst = ei + N_EDGES;

    // lazy one-time stream/event creation (happens on the uncaptured
    // correctness call; reused identically on every call -> deterministic)
    static cudaStream_t s2 = nullptr;
    static cudaEvent_t ev_fork = nullptr, ev_join = nullptr;
    if (s2 == nullptr) {
        cudaStreamCreateWithFlags(&s2, cudaStreamNonBlocking);
        cudaEventCreateWithFlags(&ev_fork, cudaEventDisableTiming);
        cudaEventCreateWithFlags(&ev_join, cudaEventDisableTiming);
    }

    dim3 gemmGrid(4, (N_NODES + 127) / 128);

    // fork: CSR build on s2, overlapped with prep + GEMM1 on main stream
    cudaEventRecord(ev_fork, 0);
    cudaStreamWaitEvent(s2, ev_fork, 0);
    k_zero_cnt<<<(N_NODES + 255) / 256, 256, 0, s2>>>();
    k_hist<<<(N_EDGES + 255) / 256, 256, 0, s2>>>(dst);
    k_scan1<<<NB_SCAN, 256, 0, s2>>>();
    k_scan2<<<1, 128, 0, s2>>>(NB_SCAN);
    k_scan3<<<(N_NODES + 255) / 256, 256, 0, s2>>>();
    k_scatter<<<(N_EDGES + 255) / 256, 256, 0, s2>>>(src, dst);
    cudaEventRecord(ev_join, s2);

    // main stream: prep + GEMM1
    k_prep_x<<<(N_NODES * 128 + 255) / 256, 256>>>(x);
    k_prep_w<<<(D * D + 255) / 256, 256>>>(W1);
    k_gemm_f16<<<gemmGrid, 256>>>(N_NODES);

    // join, then layer-1 gather
    cudaStreamWaitEvent(0, ev_join, 0);
    k_gcn<<<N_NODES, 128>>>(b1, 0);

    // layer 2
    k_prep_w<<<(D * D + 255) / 256, 256>>>(W2);
    k_gemm_f16<<<gemmGrid, 256>>>(N_NODES);
    k_gcn<<<N_NODES, 128>>>(b2, 1);

    // pool -> gx -> GRU(+classifier)
    k_pool1<<<T_STEPS * POOL_PARTS, 256>>>();
    k_pool2<<<T_STEPS, 256>>>();
    k_gx<<<(T_STEPS * 3 * D + 127) / 128, 128>>>(w_ih, b_ih);
    k_gru_reset<<<((T_STEPS + 2) * GRU_NB + 255) / 256, 256>>>();
    k_gru<<<GRU_NB, 256>>>(w_hh, b_hh, Wc, bc, out);
}

// round 12
// speedup vs baseline: 1.6211x; 1.0475x over previous
#include <cuda_runtime.h>
#include <cuda_bf16.h>
#include <cuda_fp16.h>
#include <math.h>
#include <stdint.h>

#define N_NODES 100000
#define N_EDGES 1600000
#define T_STEPS 64
#define D 256
#define D_OUT 16
#define CHUNK 1562
#define NB_SCAN 98
#define GRU_NB 32
#define GRU_UPB 8
#define POOL_PARTS 16

// ---------------- scratch ---------------------------------------------------
__device__ __align__(16) int   g_cnt[N_NODES];
__device__ __align__(16) float g_dis[N_NODES];
__device__ __align__(16) int   g_row_ptr[N_NODES + 1];
__device__ __align__(16) int   g_cursor[N_NODES];
__device__ __align__(16) int   g_csr_src[N_EDGES];
__device__ __align__(16) float g_csr_coef[N_EDGES];
__device__ __align__(16) __half g_xw16[(size_t)N_NODES * D];  // GEMM out (fp16)
__device__ __align__(16) __half g_a16[(size_t)N_NODES * D];   // GEMM A (fp16)
__device__ __align__(16) __half g_bh16[D * D];                // W^T [N][K] fp16
__device__ __align__(16) float g_pooled[T_STEPS * D];
__device__ __align__(16) float g_ppart[T_STEPS][POOL_PARTS][D];
__device__ __align__(16) float g_gx[T_STEPS * 3 * D];
__device__ __align__(16) int   g_blocksums[128];
__device__ volatile int   g_gru_flag[T_STEPS + 2][GRU_NB];
__device__ volatile float g_h[D];

// ---------------- CSR build ------------------------------------------------
__global__ void k_zero_cnt() {
    int i = blockIdx.x * blockDim.x + threadIdx.x;
    if (i < N_NODES) g_cnt[i] = 0;
}
__global__ void k_zero_ppart() {
    int i = blockIdx.x * blockDim.x + threadIdx.x;
    if (i < T_STEPS * POOL_PARTS * D) ((float*)g_ppart)[i] = 0.f;
}
__global__ void k_hist(const int* __restrict__ dst) {
    int e = blockIdx.x * blockDim.x + threadIdx.x;
    if (e < N_EDGES) {
        int d = dst[e];
        if (d >= 0 && d < N_NODES) atomicAdd(&g_cnt[d], 1);
    }
}
__global__ void k_scan1() {
    __shared__ int sh[256];
    int b = blockIdx.x, tid = threadIdx.x;
    int base = b * 1024;
    int v[4];
#pragma unroll
    for (int i = 0; i < 4; i++) {
        int idx = base + tid * 4 + i;
        v[i] = (idx < N_NODES) ? g_cnt[idx] : 0;
    }
    int s = v[0] + v[1] + v[2] + v[3];
    sh[tid] = s;
    __syncthreads();
    for (int off = 1; off < 256; off <<= 1) {
        int x = (tid >= off) ? sh[tid - off] : 0;
        __syncthreads();
        sh[tid] += x;
        __syncthreads();
    }
    int excl = sh[tid] - s;
    if (tid == 255) g_blocksums[b] = sh[255];
    int run = excl;
#pragma unroll
    for (int i = 0; i < 4; i++) {
        int idx = base + tid * 4 + i;
        if (idx < N_NODES) g_row_ptr[idx] = run;
        run += v[i];
    }
}
__global__ void k_scan2(int nb) {
    __shared__ int sh[128];
    int tid = threadIdx.x;
    int s = (tid < nb) ? g_blocksums[tid] : 0;
    sh[tid] = s;
    __syncthreads();
    for (int off = 1; off < 128; off <<= 1) {
        int x = (tid >= off) ? sh[tid - off] : 0;
        __syncthreads();
        sh[tid] += x;
        __syncthreads();
    }
    if (tid < nb) g_blocksums[tid] = sh[tid] - s;
}
__global__ void k_scan3() {
    int i = blockIdx.x * blockDim.x + threadIdx.x;
    if (i < N_NODES) {
        int v = g_row_ptr[i] + g_blocksums[i >> 10];
        g_row_ptr[i] = v;
        g_cursor[i]  = v;
        g_dis[i] = rsqrtf((float)g_cnt[i] + 1.0f);
    }
    if (i == 0) g_row_ptr[N_NODES] = N_EDGES;
}
__global__ void k_scatter(const int* __restrict__ src, const int* __restrict__ dst) {
    int e = blockIdx.x * blockDim.x + threadIdx.x;
    if (e < N_EDGES) {
        int s = src[e], d = dst[e];
        if (s < 0 || s >= N_NODES || d < 0 || d >= N_NODES) return;
        int p = atomicAdd(&g_cursor[d], 1);
        g_csr_src[p]  = s;
        g_csr_coef[p] = g_dis[s] * g_dis[d];
    }
}

// ---------------- input prep -----------------------------------------------
__global__ void k_prep_x(const float* __restrict__ x) {
    int i = blockIdx.x * blockDim.x + threadIdx.x;   // float2 index
    if (i >= N_NODES * 128) return;
    float2 v = ((const float2*)x)[i];
    __half2 h;
    h.x = __float2half(v.x);
    h.y = __float2half(v.y);
    ((__half2*)g_a16)[i] = h;
}
// W [K,N] row-major -> W^T [N][K] fp16
__global__ void k_prep_w(const float* __restrict__ W) {
    int idx = blockIdx.x * blockDim.x + threadIdx.x;  // n*256 + k
    if (idx >= D * D) return;
    int n = idx >> 8, k = idx & 255;
    g_bh16[idx] = __float2half(W[k * D + n]);
}

// ---------------- fp16 single-pass tensor GEMM ------------------------------
// block 128(M) x 128(N), 8 warps = 4Mx2N, warp tile 32(M)x64(N), BK=32.
#define APITCH 40

__device__ __forceinline__ void mma_f16(float* c, const uint32_t* a, const uint32_t* b) {
    asm volatile(
        "mma.sync.aligned.m16n8k16.row.col.f32.f16.f16.f32 "
        "{%0,%1,%2,%3}, {%4,%5,%6,%7}, {%8,%9}, {%0,%1,%2,%3};"
        : "+f"(c[0]), "+f"(c[1]), "+f"(c[2]), "+f"(c[3])
        : "r"(a[0]), "r"(a[1]), "r"(a[2]), "r"(a[3]), "r"(b[0]), "r"(b[1]));
}

__global__ __launch_bounds__(256)
void k_gemm_f16(int M) {
    __shared__ __half Ah[128][APITCH];
    __shared__ __half Bh[128][APITCH];

    int bm = blockIdx.y * 128;
    int bn = blockIdx.x * 128;
    int tid  = threadIdx.x;
    int warp = tid >> 5, lane = tid & 31;
    int wm = warp & 3;          // 0..3 (M)
    int wn = warp >> 2;         // 0..1 (N)
    int lq = lane >> 2;
    int lr = lane & 3;

    float acc[2][8][4];
#pragma unroll
    for (int i = 0; i < 2; i++)
#pragma unroll
        for (int j = 0; j < 8; j++)
#pragma unroll
            for (int v = 0; v < 4; v++) acc[i][j][v] = 0.f;

    for (int ch = 0; ch < 8; ch++) {
        int k0 = ch * 32;
        // A chunk: 128 rows x 32 fp16 = 512 uint4, 2/thread
#pragma unroll
        for (int i = 0; i < 2; i++) {
            int idx = tid + 256 * i;
            int row = idx >> 2, c = idx & 3;
            uint4 v = make_uint4(0, 0, 0, 0);
            if (bm + row < M)
                v = *(const uint4*)(g_a16 + (size_t)(bm + row) * D + k0 + c * 8);
            *(uint4*)&Ah[row][c * 8] = v;
        }
        // B chunk: 128 n-rows x 32 fp16 = 512 uint4, 2/thread
#pragma unroll
        for (int i = 0; i < 2; i++) {
            int idx = tid + 256 * i;
            int row = idx >> 2, c = idx & 3;
            size_t g = (size_t)(bn + row) * D + k0 + c * 8;
            *(uint4*)&Bh[row][c * 8] = *(const uint4*)(g_bh16 + g);
        }
        __syncthreads();

#pragma unroll
        for (int ks = 0; ks < 2; ks++) {
            int kk = ks * 16;
            uint32_t a[2][4], bF[8][2];
#pragma unroll
            for (int mt = 0; mt < 2; mt++) {
                int r = wm * 32 + mt * 16 + lq;
                a[mt][0] = *(const uint32_t*)&Ah[r    ][kk + lr * 2];
                a[mt][1] = *(const uint32_t*)&Ah[r + 8][kk + lr * 2];
                a[mt][2] = *(const uint32_t*)&Ah[r    ][kk + 8 + lr * 2];
                a[mt][3] = *(const uint32_t*)&Ah[r + 8][kk + 8 + lr * 2];
            }
#pragma unroll
            for (int nt = 0; nt < 8; nt++) {
                int n = wn * 64 + nt * 8 + lq;
                bF[nt][0] = *(const uint32_t*)&Bh[n][kk + lr * 2];
                bF[nt][1] = *(const uint32_t*)&Bh[n][kk + 8 + lr * 2];
            }
#pragma unroll
            for (int mt = 0; mt < 2; mt++)
#pragma unroll
                for (int nt = 0; nt < 8; nt++)
                    mma_f16(acc[mt][nt], a[mt], bF[nt]);
        }
        __syncthreads();
    }

#pragma unroll
    for (int mt = 0; mt < 2; mt++) {
#pragma unroll
        for (int nt = 0; nt < 8; nt++) {
            int gr0 = bm + wm * 32 + mt * 16 + lq;
            int gc  = bn + wn * 64 + nt * 8 + lr * 2;
            __half2 h0, h1;
            h0.x = __float2half(acc[mt][nt][0]);
            h0.y = __float2half(acc[mt][nt][1]);
            h1.x = __float2half(acc[mt][nt][2]);
            h1.y = __float2half(acc[mt][nt][3]);
            if (gr0 < M)
                *(__half2*)(g_xw16 + (size_t)gr0 * D + gc) = h0;
            if (gr0 + 8 < M)
                *(__half2*)(g_xw16 + (size_t)(gr0 + 8) * D + gc) = h1;
        }
    }
}

// ---------------- fused GCN aggregation (fp16 rows, single pass) ------------
// mode 0: emit fp16 (feeds next GEMM).
// mode 1: atomically accumulate into pooled partials (fused mean-pool).
__global__ __launch_bounds__(128)
void k_gcn(const float* __restrict__ bias, int mode) {
    int d   = blockIdx.x;
    int tid = threadIdx.x;
    int beg = g_row_ptr[d], end = g_row_ptr[d + 1];
    const __half2* xw = (const __half2*)g_xw16;
    float2 acc = make_float2(0.f, 0.f);
    int j = beg;
    for (; j + 3 < end; j += 4) {
        int s0 = g_csr_src[j],     s1 = g_csr_src[j + 1];
        int s2 = g_csr_src[j + 2], s3 = g_csr_src[j + 3];
        float c0 = g_csr_coef[j],     c1 = g_csr_coef[j + 1];
        float c2 = g_csr_coef[j + 2], c3 = g_csr_coef[j + 3];
        float2 v0 = __half22float2(xw[(size_t)s0 * 128 + tid]);
        float2 v1 = __half22float2(xw[(size_t)s1 * 128 + tid]);
        float2 v2 = __half22float2(xw[(size_t)s2 * 128 + tid]);
        float2 v3 = __half22float2(xw[(size_t)s3 * 128 + tid]);
        acc.x += c0 * v0.x + c1 * v1.x + c2 * v2.x + c3 * v3.x;
        acc.y += c0 * v0.y + c1 * v1.y + c2 * v2.y + c3 * v3.y;
    }
    for (; j < end; j++) {
        int s = g_csr_src[j];
        float c = g_csr_coef[j];
        float2 v = __half22float2(xw[(size_t)s * 128 + tid]);
        acc.x += c * v.x;
        acc.y += c * v.y;
    }
    float dis = g_dis[d];
    float d2 = dis * dis;
    float2 sv = __half22float2(xw[(size_t)d * 128 + tid]);
    acc.x += d2 * sv.x + bias[tid * 2];
    acc.y += d2 * sv.y + bias[tid * 2 + 1];
    acc.x = fmaxf(acc.x, 0.f);
    acc.y = fmaxf(acc.y, 0.f);
    if (mode == 1) {
        int t = d / CHUNK;
        int p = (d % CHUNK) / 98;          // 0..15
        atomicAdd(&g_ppart[t][p][tid * 2], acc.x);
        atomicAdd(&g_ppart[t][p][tid * 2 + 1], acc.y);
    } else {
        __half2 hv;
        hv.x = __float2half(acc.x);
        hv.y = __float2half(acc.y);
        ((__half2*)g_a16)[(size_t)d * 128 + tid] = hv;
    }
}

// ---------------- pool reduce ----------------------------------------------
__global__ void k_pool2() {
    int t = blockIdx.x, f = threadIdx.x;
    float acc = 0.f;
#pragma unroll
    for (int p = 0; p < POOL_PARTS; p++) acc += g_ppart[t][p][f];
    g_pooled[t * D + f] = acc * (1.0f / (float)CHUNK);
}

// ---------------- gx = pooled @ w_ih^T + b_ih ------------------------------
__global__ void k_gx(const float* __restrict__ w_ih, const float* __restrict__ b_ih) {
    int idx = blockIdx.x * blockDim.x + threadIdx.x;
    if (idx >= T_STEPS * 3 * D) return;
    int t = idx / (3 * D), j = idx % (3 * D);
    const float4* w = (const float4*)(w_ih + (size_t)j * D);
    const float4* p = (const float4*)(g_pooled + t * D);
    float acc = b_ih[j];
#pragma unroll 4
    for (int k = 0; k < D / 4; k++) {
        float4 a = w[k], b = p[k];
        acc += a.x * b.x + a.y * b.y + a.z * b.z + a.w * b.w;
    }
    g_gx[idx] = acc;
}

// ---------------- distributed GRU ------------------------------------------
__global__ void k_gru_reset() {
    int i = blockIdx.x * blockDim.x + threadIdx.x;
    if (i < (T_STEPS + 2) * GRU_NB) ((volatile int*)g_gru_flag)[i] = 0;
}
__device__ __forceinline__ void gru_barrier(int id, int b, int tid) {
    __syncthreads();
    if (tid == 0) {
        __threadfence();
        g_gru_flag[id][b] = 1;
    }
    if (tid < GRU_NB) {
        while (g_gru_flag[id][tid] == 0) { }
    }
    __syncthreads();
}
__global__ __launch_bounds__(256)
void k_gru(const float* __restrict__ w_hh, const float* __restrict__ b_hh,
           const float* __restrict__ Wc, const float* __restrict__ bc,
           float* __restrict__ out) {
    __shared__ float w_sh[3 * GRU_UPB][D];
    __shared__ float h_sh[D];
    __shared__ float gh_sh[3 * GRU_UPB];
    __shared__ float bhh_sh[3 * GRU_UPB];
    int b = blockIdx.x, tid = threadIdx.x;
    int warp = tid >> 5, lane = tid & 31;

    for (int idx = tid; idx < 3 * GRU_UPB * D; idx += 256) {
        int l = idx >> 8, k = idx & 255;
        int row = (l >> 3) * D + b * GRU_UPB + (l & 7);
        w_sh[l][k] = w_hh[(size_t)row * D + k];
    }
    if (tid < 3 * GRU_UPB) {
        int row = (tid >> 3) * D + b * GRU_UPB + (tid & 7);
        bhh_sh[tid] = b_hh[row];
    }
    if (tid < GRU_UPB) g_h[b * GRU_UPB + tid] = 0.f;
    __threadfence();
    gru_barrier(0, b, tid);

    for (int t = 0; t < T_STEPS; t++) {
        h_sh[tid] = g_h[tid];
        __syncthreads();
#pragma unroll
        for (int rr = 0; rr < 3; rr++) {
            int l = warp * 3 + rr;
            const float4* w = (const float4*)&w_sh[l][lane * 8];
            float4 a0 = w[0], a1 = w[1];
            float4 h0 = *(const float4*)&h_sh[lane * 8];
            float4 h1 = *(const float4*)&h_sh[lane * 8 + 4];
            float p = a0.x * h0.x + a0.y * h0.y + a0.z * h0.z + a0.w * h0.w
                    + a1.x * h1.x + a1.y * h1.y + a1.z * h1.z + a1.w * h1.w;
#pragma unroll
            for (int o = 16; o > 0; o >>= 1) p += __shfl_down_sync(0xffffffffu, p, o);
            if (lane == 0) gh_sh[l] = p + bhh_sh[l];
        }
        __syncthreads();
        if (tid < GRU_UPB) {
            int u = b * GRU_UPB + tid;
            float xr = g_gx[t * 3 * D + u];
            float xz = g_gx[t * 3 * D + D + u];
            float xn = g_gx[t * 3 * D + 2 * D + u];
            float r_ = 1.f / (1.f + expf(-(xr + gh_sh[tid])));
            float z_ = 1.f / (1.f + expf(-(xz + gh_sh[GRU_UPB + tid])));
            float n_ = tanhf(xn + r_ * gh_sh[2 * GRU_UPB + tid]);
            g_h[u] = (1.f - z_) * n_ + z_ * h_sh[u];
        }
        __threadfence();
        gru_barrier(t + 1, b, tid);
    }
    if (b == 0 && tid < D_OUT) {
        float acc = bc[tid];
        for (int k = 0; k < D; k++) acc += Wc[(size_t)tid * D + k] * g_h[k];
        out[tid] = acc;
    }
}

// ---------------- launch ----------------------------------------------------
extern "C" void kernel_launch(void* const* d_in, const int* in_sizes, int n_in,
                              void* d_out, int out_size) {
    int idx_x = 0, idx_ei = 1;
    if (in_sizes[idx_ei] != 2 * N_EDGES) {
        for (int i = 0; i < n_in; i++) if (in_sizes[i] == 2 * N_EDGES) { idx_ei = i; break; }
    }
    if (in_sizes[idx_x] != N_NODES * D) {
        for (int i = 0; i < n_in; i++) if (in_sizes[i] == N_NODES * D) { idx_x = i; break; }
    }

    const float* x    = (const float*)d_in[idx_x];
    const int*   ei   = (const int*)d_in[idx_ei];
    const float* W1   = (const float*)d_in[3];
    const float* b1   = (const float*)d_in[4];
    const float* W2   = (const float*)d_in[5];
    const float* b2   = (const float*)d_in[6];
    const float* w_ih = (const float*)d_in[7];
    const float* w_hh = (const float*)d_in[8];
    const float* b_ih = (const float*)d_in[9];
    const float* b_hh = (const float*)d_in[10];
    const float* Wc   = (const float*)d_in[11];
    const float* bc   = (const float*)d_in[12];
    float* out = (float*)d_out;

    const int* src = ei;
    const int* dst = ei + N_EDGES;

    static cudaStream_t s2 = nullptr;
    static cudaEvent_t ev_fork = nullptr, ev_join = nullptr;
    if (s2 == nullptr) {
        cudaStreamCreateWithFlags(&s2, cudaStreamNonBlocking);
        cudaEventCreateWithFlags(&ev_fork, cudaEventDisableTiming);
        cudaEventCreateWithFlags(&ev_join, cudaEventDisableTiming);
    }

    dim3 gemmGrid(2, (N_NODES + 127) / 128);

    // fork: CSR build + ppart zero on s2, overlapped with prep + GEMM1
    cudaEventRecord(ev_fork, 0);
    cudaStreamWaitEvent(s2, ev_fork, 0);
    k_zero_cnt<<<(N_NODES + 255) / 256, 256, 0, s2>>>();
    k_zero_ppart<<<(T_STEPS * POOL_PARTS * D + 255) / 256, 256, 0, s2>>>();
    k_hist<<<(N_EDGES + 255) / 256, 256, 0, s2>>>(dst);
    k_scan1<<<NB_SCAN, 256, 0, s2>>>();
    k_scan2<<<1, 128, 0, s2>>>(NB_SCAN);
    k_scan3<<<(N_NODES + 255) / 256, 256, 0, s2>>>();
    k_scatter<<<(N_EDGES + 255) / 256, 256, 0, s2>>>(src, dst);
    cudaEventRecord(ev_join, s2);

    // main stream: prep + GEMM1
    k_prep_x<<<(N_NODES * 128 + 255) / 256, 256>>>(x);
    k_prep_w<<<(D * D + 255) / 256, 256>>>(W1);
    k_gemm_f16<<<gemmGrid, 256>>>(N_NODES);

    // join, then layer-1 gather
    cudaStreamWaitEvent(0, ev_join, 0);
    k_gcn<<<N_NODES, 128>>>(b1, 0);

    // layer 2 (gather fused with mean-pool accumulation)
    k_prep_w<<<(D * D + 255) / 256, 256>>>(W2);
    k_gemm_f16<<<gemmGrid, 256>>>(N_NODES);
    k_gcn<<<N_NODES, 128>>>(b2, 1);

    // pool reduce -> gx -> GRU(+classifier)
    k_pool2<<<T_STEPS, 256>>>();
    k_gx<<<(T_STEPS * 3 * D + 127) / 128, 128>>>(w_ih, b_ih);
    k_gru_reset<<<((T_STEPS + 2) * GRU_NB + 255) / 256, 256>>>();
    k_gru<<<GRU_NB, 256>>>(w_hh, b_hh, Wc, bc, out);
}